// round 1
// baseline (speedup 1.0000x reference)
#include <cuda_runtime.h>
#include <math.h>

#define D 48
#define D2 (48*48)
#define D3 (48*48*48)
#define WTOT 4680           // windows per (b,head): 4096+512+64+8
#define LTOK 27
#define NTOK (LTOK*8)       // 216 floats per window per head

// Per-window attention output tokens: [b*2+head][window][27][8]
__device__ float g_attn[8 * WTOT * NTOK];   // ~32.3 MB static scratch

__global__ __launch_bounds__(256) void phaseA(
    const float* __restrict__ Q, const float* __restrict__ K,
    const float* __restrict__ V, const float* __restrict__ tab)
{
    __shared__ float sT[3][NTOK];   // pooled q,k,v tokens
    __shared__ float sTab[250];     // rpb table (125 x 2)
    __shared__ float sS[27*27];     // scores -> weights

    const int bid  = blockIdx.x;
    const int bh   = bid & 7;       // b*2+head
    const int wrev = bid >> 3;      // big branches first
    const int b    = bh >> 1;
    const int head = bh & 1;

    int branch, wi;
    if      (wrev < 8)   { branch = 3; wi = wrev;       }
    else if (wrev < 72)  { branch = 2; wi = wrev - 8;   }
    else if (wrev < 584) { branch = 1; wi = wrev - 72;  }
    else                 { branch = 0; wi = wrev - 584; }

    const int bw = 3 << branch;     // 3,6,12,24
    const int sw = 1 << branch;     // 1,2,4,8
    const int Nw = 16 >> branch;    // 16,8,4,2

    const int tid = threadIdx.x;
    for (int i = tid; i < 250; i += 256) sTab[i] = tab[i];

    const int wh = wi / (Nw * Nw);
    const int rm = wi - wh * Nw * Nw;
    const int ww = rm / Nw;
    const int wd = rm - ww * Nw;
    const int h0 = wh * bw, w0 = ww * bw, d0 = wd * bw;
    const int chbase = b * 64 + branch * 16 + head * 8;

    // ---- max-pool gather: 3 tensors x 27 tokens x 8 channels ----
    for (int s = tid; s < 648; s += 256) {
        const int t = s / 216;
        const int r = s - t * 216;
        const int m = r >> 3;
        const int c = r & 7;
        const int th = m / 9, tw = (m / 3) % 3, td = m % 3;
        const float* base = (t == 0 ? Q : (t == 1 ? K : V))
                            + (size_t)(chbase + c) * D3;
        const int hh = h0 + th * sw, wwp = w0 + tw * sw, dd0 = d0 + td * sw;
        float mx = -1e30f;
        if (sw >= 4) {
            for (int dh = 0; dh < sw; dh++)
                for (int dw = 0; dw < sw; dw++) {
                    const float4* p = (const float4*)(base + ((size_t)(hh + dh) * D + (wwp + dw)) * D + dd0);
                    #pragma unroll
                    for (int dd = 0; dd < 2; dd++) {        // sw/4 <= 2
                        if (dd * 4 < sw) {
                            float4 v4 = __ldg(p + dd);
                            mx = fmaxf(mx, fmaxf(fmaxf(v4.x, v4.y), fmaxf(v4.z, v4.w)));
                        }
                    }
                }
        } else {
            for (int dh = 0; dh < sw; dh++)
                for (int dw = 0; dw < sw; dw++) {
                    const float* p = base + ((size_t)(hh + dh) * D + (wwp + dw)) * D + dd0;
                    for (int dd = 0; dd < sw; dd++) mx = fmaxf(mx, __ldg(p + dd));
                }
        }
        sT[t][r] = mx;
    }
    __syncthreads();

    // ---- scores = q k^T / sqrt(8) ----
    const float inv_scale = 0.3535533905932738f;
    for (int s = tid; s < 729; s += 256) {
        const int m = s / 27, n = s - m * 27;
        float acc = 0.f;
        #pragma unroll
        for (int c = 0; c < 8; c++) acc += sT[0][m * 8 + c] * sT[1][n * 8 + c];
        sS[s] = acc * inv_scale;
    }
    __syncthreads();

    // ---- softmax per row, then add rel-pos bias (post-softmax!) ----
    if (tid < 27) {
        const int m = tid;
        float mx = -1e30f;
        for (int n = 0; n < 27; n++) mx = fmaxf(mx, sS[m * 27 + n]);
        float sum = 0.f;
        for (int n = 0; n < 27; n++) {
            float e = __expf(sS[m * 27 + n] - mx);
            sS[m * 27 + n] = e;
            sum += e;
        }
        const float inv = 1.0f / sum;
        const int mh = m / 9, mw = (m / 3) % 3, md = m % 3;
        for (int n = 0; n < 27; n++) {
            const int nh = n / 9, nw = (n / 3) % 3, nd = n % 3;
            const int idx = ((mh - nh + 2) * 5 + (mw - nw + 2)) * 5 + (md - nd + 2);
            sS[m * 27 + n] = sS[m * 27 + n] * inv + sTab[idx * 2 + head];
        }
    }
    __syncthreads();

    // ---- attn = weights @ v -> global scratch ----
    const int O[4] = {0, 4096, 4608, 4672};
    float* outp = g_attn + ((size_t)bh * WTOT + (O[branch] + wi)) * NTOK;
    for (int s = tid; s < 216; s += 256) {
        const int m = s >> 3, c = s & 7;
        float acc = 0.f;
        #pragma unroll
        for (int n = 0; n < 27; n++) acc += sS[m * 27 + n] * sT[2][n * 8 + c];
        outp[s] = acc;
    }
}

__global__ __launch_bounds__(256) void phaseB(float* __restrict__ out)
{
    // grid: b(4) x head(2) x branch(4) x uh(48) = 1536 CTAs
    const int bid  = blockIdx.x;
    const int uh   = bid % 48;
    const int br   = (bid / 48) & 3;
    const int head = (bid / 192) & 1;
    const int b    = bid / 384;

    const int bw = 3 << br;
    const int Nw = 16 >> br;

    __shared__ int   s_win[48];
    __shared__ int   s_i0[48];
    __shared__ float s_f[48];

    const int tid = threadIdx.x;
    if (tid < 48) {
        const int u    = tid;
        const int wwin = u / bw;
        const int uin  = u - wwin * bw;
        const float step = 2.0f / (float)(bw - 1);
        float pos = (float)uin * step;
        int i0 = (int)floorf(pos);
        if (i0 > 2) i0 = 2;
        if (i0 < 0) i0 = 0;
        s_win[u] = wwin;
        s_i0[u]  = i0;
        s_f[u]   = pos - (float)i0;
    }
    __syncthreads();

    const int   wh  = s_win[uh];
    const int   ih0 = s_i0[uh];
    const int   ih1 = min(ih0 + 1, 2);
    const float fh  = s_f[uh];

    const int O[4] = {0, 4096, 4608, 4672};
    const size_t bhW = (size_t)(b * 2 + head) * WTOT;
    float* oplane = out + (size_t)(b * 64 + br * 16 + head * 8) * D3 + (size_t)uh * D2;

    for (int idx = tid; idx < 8 * 48 * 48; idx += 256) {
        const int ud = idx % 48;
        const int t2 = idx / 48;
        const int uw = t2 % 48;
        const int c  = t2 / 48;

        const int   wwn = s_win[uw];
        const int   iw0 = s_i0[uw];
        const int   iw1 = min(iw0 + 1, 2);
        const float fw  = s_f[uw];
        const int   wdn = s_win[ud];
        const int   id0 = s_i0[ud];
        const int   id1 = min(id0 + 1, 2);
        const float fd  = s_f[ud];

        const int wstore = O[br] + (wh * Nw + wwn) * Nw + wdn;
        const float* a = g_attn + (bhW + wstore) * NTOK + c;

        const float v000 = __ldg(a + ((ih0 * 3 + iw0) * 3 + id0) * 8);
        const float v001 = __ldg(a + ((ih0 * 3 + iw0) * 3 + id1) * 8);
        const float v010 = __ldg(a + ((ih0 * 3 + iw1) * 3 + id0) * 8);
        const float v011 = __ldg(a + ((ih0 * 3 + iw1) * 3 + id1) * 8);
        const float v100 = __ldg(a + ((ih1 * 3 + iw0) * 3 + id0) * 8);
        const float v101 = __ldg(a + ((ih1 * 3 + iw0) * 3 + id1) * 8);
        const float v110 = __ldg(a + ((ih1 * 3 + iw1) * 3 + id0) * 8);
        const float v111 = __ldg(a + ((ih1 * 3 + iw1) * 3 + id1) * 8);

        const float c00 = v000 + fd * (v001 - v000);
        const float c01 = v010 + fd * (v011 - v010);
        const float c10 = v100 + fd * (v101 - v100);
        const float c11 = v110 + fd * (v111 - v110);
        const float c0  = c00 + fw * (c01 - c00);
        const float c1  = c10 + fw * (c11 - c10);

        oplane[(size_t)c * D3 + uw * 48 + ud] = c0 + fh * (c1 - c0);
    }
}

extern "C" void kernel_launch(void* const* d_in, const int* in_sizes, int n_in,
                              void* d_out, int out_size)
{
    const float* Q   = (const float*)d_in[0];
    const float* K   = (const float*)d_in[1];
    const float* V   = (const float*)d_in[2];
    const float* tab = (const float*)d_in[3];
    float* out = (float*)d_out;

    phaseA<<<WTOT * 8, 256>>>(Q, K, V, tab);
    phaseB<<<4 * 2 * 4 * 48, 256>>>(out);
}

// round 2
// speedup vs baseline: 1.3982x; 1.3982x over previous
#include <cuda_runtime.h>
#include <math.h>

#define D 48
#define D2 (48*48)
#define D3 (48*48*48)
#define WTOT 4680           // windows per (b,head): 4096+512+64+8

// Scratch layout: [bh(8)][m*8+c (216)][window (4680)]  -> window innermost
__device__ float g_attn[8 * 216 * WTOT];   // ~32.3 MB

__global__ __launch_bounds__(256) void phaseA(
    const float* __restrict__ Q, const float* __restrict__ K,
    const float* __restrict__ V, const float* __restrict__ tab)
{
    // pooled tokens: [t(3)][c(8)][th*3+tw (9)][pd (<=48)]  (fixed stride 48)
    __shared__ float sP[3 * 8 * 9 * 48];    // 41472 B
    __shared__ float sTab[250];

    const int cid = blockIdx.x;
    int br, rem;
    if      (cid < 32)  { br = 3; rem = cid;       }
    else if (cid < 160) { br = 2; rem = cid - 32;  }
    else if (cid < 672) { br = 1; rem = cid - 160; }
    else                { br = 0; rem = cid - 672; }

    const int Nw   = 16 >> br;      // 16,8,4,2
    const int NwSq = Nw * Nw;
    const int bh   = rem / NwSq;
    const int wc   = rem - bh * NwSq;
    const int wh   = wc / Nw;
    const int ww   = wc - wh * Nw;
    const int b    = bh >> 1;
    const int head = bh & 1;
    const int sw   = 1 << br;       // 1,2,4,8
    const int bw   = 3 << br;       // 3,6,12,24
    const int tid  = threadIdx.x;

    for (int i = tid; i < 250; i += 256) sTab[i] = tab[i];

    const int chbase = b * 64 + br * 16 + head * 8;
    const int Ppd = 3 * Nw;                 // pooled-d count
    const int E   = 3 * 8 * 9 * Ppd;        // pooled elems this CTA
    const int h0w = wh * bw, w0w = ww * bw;

    // ---- coalesced max-pool of the full d-line for 3 tensors x 8 ch x 9 (th,tw) ----
    for (int e = tid; e < E; e += 256) {
        const int pd  = e % Ppd;
        const int r   = e / Ppd;
        const int thw = r % 9;
        const int c   = (r / 9) & 7;
        const int t   = r / 72;
        const int th  = thw / 3, tw = thw % 3;

        const float* base = (t == 0 ? Q : (t == 1 ? K : V))
                            + (size_t)(chbase + c) * D3;
        const int hh  = h0w + th * sw;
        const int wwp = w0w + tw * sw;
        const int dd0 = pd * sw;

        float mx = -1e30f;
        if (sw == 1) {
            mx = __ldg(base + (hh * D + wwp) * D + dd0);
        } else if (sw == 2) {
            #pragma unroll
            for (int dh = 0; dh < 2; dh++)
                #pragma unroll
                for (int dw = 0; dw < 2; dw++) {
                    float2 v2 = __ldg((const float2*)(base + ((hh + dh) * D + (wwp + dw)) * D + dd0));
                    mx = fmaxf(mx, fmaxf(v2.x, v2.y));
                }
        } else {
            for (int dh = 0; dh < sw; dh++)
                for (int dw = 0; dw < sw; dw++) {
                    const float4* p = (const float4*)(base + ((size_t)(hh + dh) * D + (wwp + dw)) * D + dd0);
                    #pragma unroll
                    for (int k4 = 0; k4 < 2; k4++) {
                        if (k4 * 4 < sw) {
                            float4 v4 = __ldg(p + k4);
                            mx = fmaxf(mx, fmaxf(fmaxf(v4.x, v4.y), fmaxf(v4.z, v4.w)));
                        }
                    }
                }
        }
        sP[((t * 8 + c) * 9 + thw) * 48 + pd] = mx;
    }
    __syncthreads();

    // ---- attention: one warp per window along d ----
    const int warp = tid >> 5, lane = tid & 31;
    const int Obr[4] = {0, 4096, 4608, 4672};
    const float inv_scale = 0.3535533905932738f;

    const int m  = lane;
    const int mh = m / 9, mw = (m / 3) % 3, md = m % 3;

    for (int wd = warp; wd < Nw; wd += 8) {
        if (lane < 27) {
            const int wd3 = wd * 3;
            float q[8];
            #pragma unroll
            for (int c = 0; c < 8; c++)
                q[c] = sP[(c * 9 + mh * 3 + mw) * 48 + wd3 + md];

            float s[27];
            #pragma unroll
            for (int n = 0; n < 27; n++) {
                const int nh = n / 9, nw = (n / 3) % 3, nd = n % 3;
                float acc = 0.f;
                #pragma unroll
                for (int c = 0; c < 8; c++)
                    acc += q[c] * sP[((8 + c) * 9 + nh * 3 + nw) * 48 + wd3 + nd];
                s[n] = acc * inv_scale;
            }
            float mxv = s[0];
            #pragma unroll
            for (int n = 1; n < 27; n++) mxv = fmaxf(mxv, s[n]);
            float sum = 0.f;
            #pragma unroll
            for (int n = 0; n < 27; n++) { s[n] = __expf(s[n] - mxv); sum += s[n]; }
            const float inv = 1.0f / sum;
            #pragma unroll
            for (int n = 0; n < 27; n++) {
                const int nh = n / 9, nw = (n / 3) % 3, nd = n % 3;
                const int idx = ((mh - nh + 2) * 5 + (mw - nw + 2)) * 5 + (md - nd + 2);
                s[n] = s[n] * inv + sTab[idx * 2 + head];
            }
            const size_t wbase = (size_t)Obr[br] + (size_t)(wh * Nw + ww) * Nw + wd;
            #pragma unroll
            for (int c = 0; c < 8; c++) {
                float acc = 0.f;
                #pragma unroll
                for (int n = 0; n < 27; n++) {
                    const int nh = n / 9, nw = (n / 3) % 3, nd = n % 3;
                    acc += s[n] * sP[((16 + c) * 9 + nh * 3 + nw) * 48 + wd3 + nd];
                }
                g_attn[((size_t)bh * 216 + m * 8 + c) * WTOT + wbase] = acc;
            }
        }
    }
}

__global__ __launch_bounds__(256) void phaseB(float* __restrict__ out)
{
    // grid: b(4) x head(2) x branch(4) x uh(48) = 1536 CTAs
    const int bid  = blockIdx.x;
    const int uh   = bid % 48;
    const int br   = (bid / 48) & 3;
    const int head = (bid / 192) & 1;
    const int b    = bid / 384;

    const int bw = 3 << br;
    const int Nw = 16 >> br;

    __shared__ int   s_win[48];
    __shared__ int   s_i0[48];
    __shared__ float s_f[48];

    const int tid = threadIdx.x;
    if (tid < 48) {
        const int wwin = tid / bw;
        const int uin  = tid - wwin * bw;
        float pos = (float)uin * (2.0f / (float)(bw - 1));
        int i0 = (int)floorf(pos);
        if (i0 > 2) i0 = 2;
        if (i0 < 0) i0 = 0;
        s_win[tid] = wwin;
        s_i0[tid]  = i0;
        s_f[tid]   = pos - (float)i0;
    }
    __syncthreads();

    const int   wh  = s_win[uh];
    const int   ih0 = s_i0[uh];
    const int   ih1 = min(ih0 + 1, 2);
    const float fh  = s_f[uh];

    const int Obr[4] = {0, 4096, 4608, 4672};
    const int bh2 = b * 2 + head;
    float* oplane = out + (size_t)(b * 64 + br * 16 + head * 8) * D3 + (size_t)uh * D2;

    for (int idx = tid; idx < 8 * 48 * 48; idx += 256) {
        const int ud = idx % 48;
        const int t2 = idx / 48;
        const int uw = t2 % 48;
        const int c  = t2 / 48;

        const int   iw0 = s_i0[uw];
        const int   iw1 = min(iw0 + 1, 2);
        const float fw  = s_f[uw];
        const int   id0 = s_i0[ud];
        const int   id1 = min(id0 + 1, 2);
        const float fd  = s_f[ud];

        const int win = Obr[br] + (wh * Nw + s_win[uw]) * Nw + s_win[ud];
        const float* p = g_attn + ((size_t)bh2 * 216 + c) * WTOT + win;

        #define CORNER(ih, iw, id) __ldg(p + (size_t)((((ih) * 3 + (iw)) * 3 + (id)) * 8) * WTOT)
        const float v000 = CORNER(ih0, iw0, id0);
        const float v001 = CORNER(ih0, iw0, id1);
        const float v010 = CORNER(ih0, iw1, id0);
        const float v011 = CORNER(ih0, iw1, id1);
        const float v100 = CORNER(ih1, iw0, id0);
        const float v101 = CORNER(ih1, iw0, id1);
        const float v110 = CORNER(ih1, iw1, id0);
        const float v111 = CORNER(ih1, iw1, id1);
        #undef CORNER

        const float c00 = v000 + fd * (v001 - v000);
        const float c01 = v010 + fd * (v011 - v010);
        const float c10 = v100 + fd * (v101 - v100);
        const float c11 = v110 + fd * (v111 - v110);
        const float c0  = c00 + fw * (c01 - c00);
        const float c1  = c10 + fw * (c11 - c10);

        oplane[(size_t)c * D3 + uw * 48 + ud] = c0 + fh * (c1 - c0);
    }
}

extern "C" void kernel_launch(void* const* d_in, const int* in_sizes, int n_in,
                              void* d_out, int out_size)
{
    const float* Q   = (const float*)d_in[0];
    const float* K   = (const float*)d_in[1];
    const float* V   = (const float*)d_in[2];
    const float* tab = (const float*)d_in[3];
    float* out = (float*)d_out;

    phaseA<<<2720, 256>>>(Q, K, V, tab);
    phaseB<<<1536, 256>>>(out);
}

// round 3
// speedup vs baseline: 1.6940x; 1.2116x over previous
#include <cuda_runtime.h>
#include <math.h>

#define D  48
#define D2 (48*48)
#define D3 (48*48*48)

// pooled-token scratch for branches 3,2,1 (thread-id-linear layout)
#define S3 41472          // br3: 3t*8bh*4lines*8c*9thw*6pd
#define S2 331776         // br2: 3*8*16*8*9*12
#define S1 2654208        // br1: 3*8*64*8*9*24
#define TOTPOOL (S3+S2+S1)

__device__ float g_pool[TOTPOOL];

// ---------------------------------------------------------------------------
// K1: max-pool br1..3.  One thread per pooled element.
// layout: seg(br3|br2|br1) -> ((t*8+bh)*Nw2 + line)*(72*Ppd) + (c*9+thw)*Ppd + pd
// ---------------------------------------------------------------------------
__global__ __launch_bounds__(256) void poolK(
    const float* __restrict__ Q, const float* __restrict__ Kt,
    const float* __restrict__ V)
{
    const int idx = blockIdx.x * 256 + threadIdx.x;
    if (idx >= TOTPOOL) return;

    float mx = -1e30f;

    if (idx < S3) {                       // br3: sw=8, bw=24, Nw=2, Ppd=6
        const int sub = idx;
        const int r   = sub % 432;        // 72*6
        const int q1  = sub / 432;
        const int line = q1 & 3;
        const int tb   = q1 >> 2;
        const int bh = tb & 7, t = tb >> 3;
        const int pd = r % 6, cthw = r / 6;
        const int thw = cthw % 9, c = cthw / 9;
        const float* base = (t == 0 ? Q : (t == 1 ? Kt : V))
            + (size_t)((bh >> 1) * 64 + 48 + (bh & 1) * 8 + c) * D3;
        const int hh0 = (line >> 1) * 24 + (thw / 3) * 8;
        const int ww0 = (line & 1) * 24 + (thw % 3) * 8;
        const int dd0 = pd * 8;
        for (int dh = 0; dh < 8; dh++) {
            const float* rowb = base + (size_t)(hh0 + dh) * D2 + ww0 * D + dd0;
            #pragma unroll
            for (int dw = 0; dw < 8; dw++) {
                float4 a = __ldg((const float4*)(rowb + dw * D));
                float4 b = __ldg((const float4*)(rowb + dw * D + 4));
                mx = fmaxf(mx, fmaxf(fmaxf(a.x, a.y), fmaxf(a.z, a.w)));
                mx = fmaxf(mx, fmaxf(fmaxf(b.x, b.y), fmaxf(b.z, b.w)));
            }
        }
    } else if (idx < S3 + S2) {           // br2: sw=4, bw=12, Nw=4, Ppd=12
        const int sub = idx - S3;
        const int r   = sub % 864;        // 72*12
        const int q1  = sub / 864;
        const int line = q1 & 15;
        const int tb   = q1 >> 4;
        const int bh = tb & 7, t = tb >> 3;
        const int pd = r % 12, cthw = r / 12;
        const int thw = cthw % 9, c = cthw / 9;
        const float* base = (t == 0 ? Q : (t == 1 ? Kt : V))
            + (size_t)((bh >> 1) * 64 + 32 + (bh & 1) * 8 + c) * D3;
        const int hh0 = (line >> 2) * 12 + (thw / 3) * 4;
        const int ww0 = (line & 3) * 12 + (thw % 3) * 4;
        const int dd0 = pd * 4;
        #pragma unroll
        for (int dh = 0; dh < 4; dh++) {
            const float* rowb = base + (size_t)(hh0 + dh) * D2 + ww0 * D + dd0;
            #pragma unroll
            for (int dw = 0; dw < 4; dw++) {
                float4 a = __ldg((const float4*)(rowb + dw * D));
                mx = fmaxf(mx, fmaxf(fmaxf(a.x, a.y), fmaxf(a.z, a.w)));
            }
        }
    } else {                              // br1: sw=2, bw=6, Nw=8, Ppd=24
        const int sub = idx - S3 - S2;
        const int r   = sub % 1728;       // 72*24
        const int q1  = sub / 1728;
        const int line = q1 & 63;
        const int tb   = q1 >> 6;
        const int bh = tb & 7, t = tb >> 3;
        const int pd = r % 24, cthw = r / 24;
        const int thw = cthw % 9, c = cthw / 9;
        const float* base = (t == 0 ? Q : (t == 1 ? Kt : V))
            + (size_t)((bh >> 1) * 64 + 16 + (bh & 1) * 8 + c) * D3;
        const int hh0 = (line >> 3) * 6 + (thw / 3) * 2;
        const int ww0 = (line & 7) * 6 + (thw % 3) * 2;
        const int dd0 = pd * 2;
        #pragma unroll
        for (int dh = 0; dh < 2; dh++) {
            const float* rowb = base + (size_t)(hh0 + dh) * D2 + ww0 * D + dd0;
            #pragma unroll
            for (int dw = 0; dw < 2; dw++) {
                float2 a = __ldg((const float2*)(rowb + dw * D));
                mx = fmaxf(mx, fmaxf(a.x, a.y));
            }
        }
    }
    g_pool[idx] = mx;
}

// ---------------------------------------------------------------------------
// K2: attention + window-local trilinear upsample, fused.
// CTA per (bh, br, wh, ww [, split]).  Attention tokens stored back into the
// q region of sP (each warp only reads its own window's q before overwrite).
// ---------------------------------------------------------------------------
__global__ __launch_bounds__(256) void attnK(
    const float* __restrict__ Q, const float* __restrict__ Kt,
    const float* __restrict__ V, const float* __restrict__ tab,
    float* __restrict__ out)
{
    __shared__ float sP[3 * 72 * 48];     // [t][c][thw][pd stride 48] : 41472 B
    __shared__ float sTab[250];
    __shared__ int   sI0[24];
    __shared__ float sF[24];

    const int cid = blockIdx.x;
    int br, bh, wh, ww, line, split = 0;
    if (cid < 256) {                      // br3, split x8
        br = 3; bh = cid >> 5;
        const int t5 = cid & 31;
        line = t5 >> 3; split = t5 & 7;
        wh = line >> 1; ww = line & 1;
    } else if (cid < 384) {
        br = 2; const int s = cid - 256;
        bh = s >> 4; line = s & 15;
        wh = line >> 2; ww = line & 3;
    } else if (cid < 896) {
        br = 1; const int s = cid - 384;
        bh = s >> 6; line = s & 63;
        wh = line >> 3; ww = line & 7;
    } else {
        br = 0; const int s = cid - 896;
        bh = s >> 8; line = s & 255;
        wh = line >> 4; ww = line & 15;
    }

    const int Nw  = 16 >> br;
    const int sw  = 1 << br;
    const int bw  = 3 << br;
    const int Ppd = 3 * Nw;
    const int tid = threadIdx.x;
    const int b = bh >> 1, head = bh & 1;
    const int chbase = b * 64 + br * 16 + head * 8;
    const int h0 = wh * bw, w0 = ww * bw;

    for (int i = tid; i < 250; i += 256) sTab[i] = tab[i];
    if (tid < bw) {
        const float pos = (float)tid * (2.0f / (float)(bw - 1));
        int i0 = (int)pos;
        if (i0 > 2) i0 = 2;
        sI0[tid] = i0;
        sF[tid]  = pos - (float)i0;
    }

    // ---- gather pooled tokens ----
    if (br == 0) {
        // identity pooling straight from input, coalesced over d
        for (int e = tid; e < 3 * 72 * 48; e += 256) {
            const int pd = e % 48;
            const int r  = e / 48;
            const int thw = r % 9;
            const int c   = (r / 9) & 7;
            const int t   = r / 72;
            const float* base = (t == 0 ? Q : (t == 1 ? Kt : V))
                                + (size_t)(chbase + c) * D3;
            const int hh  = h0 + thw / 3;
            const int wwp = w0 + thw % 3;
            sP[(t * 72 + c * 9 + thw) * 48 + pd] =
                __ldg(base + (hh * D + wwp) * D + pd);
        }
    } else {
        const int per = 72 * Ppd;
        const int Nw2 = Nw * Nw;
        const int base_br = (br == 3) ? 0 : (br == 2 ? S3 : S3 + S2);
        for (int e = tid; e < 3 * per; e += 256) {
            const int t = e / per;
            const int r = e - t * per;
            const int cthw = r / Ppd;
            const int pd   = r - cthw * Ppd;
            sP[(t * 72 + cthw) * 48 + pd] =
                g_pool[base_br + ((size_t)(t * 8 + bh) * Nw2 + line) * per + r];
        }
    }
    __syncthreads();

    // ---- attention: warp per window along d; tokens written into q region ----
    const int warp = tid >> 5, lane = tid & 31;
    const float inv_scale = 0.3535533905932738f;
    const int m  = lane;
    const int mh = m / 9, mw = (m / 3) % 3, md = m % 3;

    for (int wd = warp; wd < Nw; wd += 8) {
        if (lane < 27) {
            const int wd3 = wd * 3;
            float q[8];
            #pragma unroll
            for (int c = 0; c < 8; c++)
                q[c] = sP[(c * 9 + mh * 3 + mw) * 48 + wd3 + md];

            float s[27];
            #pragma unroll
            for (int n = 0; n < 27; n++) {
                const int nh = n / 9, nw = (n / 3) % 3, nd = n % 3;
                float acc = 0.f;
                #pragma unroll
                for (int c = 0; c < 8; c++)
                    acc += q[c] * sP[((8 + c) * 9 + nh * 3 + nw) * 48 + wd3 + nd];
                s[n] = acc * inv_scale;
            }
            float mxv = s[0];
            #pragma unroll
            for (int n = 1; n < 27; n++) mxv = fmaxf(mxv, s[n]);
            float sum = 0.f;
            #pragma unroll
            for (int n = 0; n < 27; n++) { s[n] = __expf(s[n] - mxv); sum += s[n]; }
            const float inv = 1.0f / sum;
            #pragma unroll
            for (int n = 0; n < 27; n++) {
                const int nh = n / 9, nw = (n / 3) % 3, nd = n % 3;
                const int idx = ((mh - nh + 2) * 5 + (mw - nw + 2)) * 5 + (md - nd + 2);
                s[n] = s[n] * inv + sTab[idx * 2 + head];
            }
            // attn token (m,c) -> reuse q slot of token m in this window
            #pragma unroll
            for (int c = 0; c < 8; c++) {
                float acc = 0.f;
                #pragma unroll
                for (int n = 0; n < 27; n++) {
                    const int nh = n / 9, nw = (n / 3) % 3, nd = n % 3;
                    acc += s[n] * sP[((16 + c) * 9 + nh * 3 + nw) * 48 + wd3 + nd];
                }
                sP[(c * 9 + mh * 3 + mw) * 48 + wd3 + md] = acc;
            }
        }
    }
    __syncthreads();

    // ---- window-local trilinear upsample -> output ----
    const size_t chD3 = (size_t)chbase * D3;
    const int total = 8 * bw * bw * 48;
    const int chunk = (br == 3) ? (total >> 3) : total;
    const int e0 = split * chunk, e1 = e0 + chunk;

    for (int e = e0 + tid; e < e1; e += 256) {
        const int d  = e % 48;
        int r        = e / 48;
        const int lw = r % bw; r /= bw;
        const int lh = r % bw;
        const int c  = r / bw;
        const int wd = d / bw;
        const int ld = d - wd * bw;
        const int wd3 = wd * 3;

        float val;
        if (br == 0) {
            val = sP[(c * 9 + lh * 3 + lw) * 48 + wd3 + ld];
        } else {
            const int ih0 = sI0[lh], iw0 = sI0[lw], id0 = sI0[ld];
            const int ih1 = min(ih0 + 1, 2), iw1 = min(iw0 + 1, 2), id1 = min(id0 + 1, 2);
            const float fh = sF[lh], fw = sF[lw], fd = sF[ld];
            const int cb = c * 9;
            #define TOK(ih, iw, id) sP[(cb + (ih) * 3 + (iw)) * 48 + wd3 + (id)]
            const float v000 = TOK(ih0, iw0, id0), v001 = TOK(ih0, iw0, id1);
            const float v010 = TOK(ih0, iw1, id0), v011 = TOK(ih0, iw1, id1);
            const float v100 = TOK(ih1, iw0, id0), v101 = TOK(ih1, iw0, id1);
            const float v110 = TOK(ih1, iw1, id0), v111 = TOK(ih1, iw1, id1);
            #undef TOK
            const float c00 = v000 + fd * (v001 - v000);
            const float c01 = v010 + fd * (v011 - v010);
            const float c10 = v100 + fd * (v101 - v100);
            const float c11 = v110 + fd * (v111 - v110);
            const float c0  = c00 + fw * (c01 - c00);
            const float c1  = c10 + fw * (c11 - c10);
            val = c0 + fh * (c1 - c0);
        }
        out[chD3 + (size_t)c * D3 + (h0 + lh) * D2 + (w0 + lw) * D + d] = val;
    }
}

extern "C" void kernel_launch(void* const* d_in, const int* in_sizes, int n_in,
                              void* d_out, int out_size)
{
    const float* Q   = (const float*)d_in[0];
    const float* K   = (const float*)d_in[1];
    const float* V   = (const float*)d_in[2];
    const float* tab = (const float*)d_in[3];
    float* out = (float*)d_out;

    poolK<<<(TOTPOOL + 255) / 256, 256>>>(Q, K, V);
    attnK<<<2944, 256>>>(Q, K, V, tab, out);
}

// round 4
// speedup vs baseline: 2.0712x; 1.2227x over previous
#include <cuda_runtime.h>
#include <math.h>

#define D  48
#define D2 (48*48)
#define D3 (48*48*48)

// pooled-token scratch for branches 3,2,1 (thread-id-linear layout)
#define S3 41472
#define S2 331776
#define S1 2654208
#define TOTPOOL (S3+S2+S1)

__device__ float g_pool[TOTPOOL];

// ---------------------------------------------------------------------------
// K1: max-pool br1..3.  One thread per pooled element.
// ---------------------------------------------------------------------------
__global__ __launch_bounds__(256) void poolK(
    const float* __restrict__ Q, const float* __restrict__ Kt,
    const float* __restrict__ V)
{
    const int idx = blockIdx.x * 256 + threadIdx.x;
    if (idx >= TOTPOOL) return;

    float mx = -1e30f;

    if (idx < S3) {                       // br3: sw=8
        const int sub = idx;
        const int r   = sub % 432;
        const int q1  = sub / 432;
        const int line = q1 & 3;
        const int tb   = q1 >> 2;
        const int bh = tb & 7, t = tb >> 3;
        const int pd = r % 6, cthw = r / 6;
        const int thw = cthw % 9, c = cthw / 9;
        const float* base = (t == 0 ? Q : (t == 1 ? Kt : V))
            + (size_t)((bh >> 1) * 64 + 48 + (bh & 1) * 8 + c) * D3;
        const int hh0 = (line >> 1) * 24 + (thw / 3) * 8;
        const int ww0 = (line & 1) * 24 + (thw % 3) * 8;
        const int dd0 = pd * 8;
        for (int dh = 0; dh < 8; dh++) {
            const float* rowb = base + (size_t)(hh0 + dh) * D2 + ww0 * D + dd0;
            #pragma unroll
            for (int dw = 0; dw < 8; dw++) {
                float4 a = __ldg((const float4*)(rowb + dw * D));
                float4 b = __ldg((const float4*)(rowb + dw * D + 4));
                mx = fmaxf(mx, fmaxf(fmaxf(a.x, a.y), fmaxf(a.z, a.w)));
                mx = fmaxf(mx, fmaxf(fmaxf(b.x, b.y), fmaxf(b.z, b.w)));
            }
        }
    } else if (idx < S3 + S2) {           // br2: sw=4
        const int sub = idx - S3;
        const int r   = sub % 864;
        const int q1  = sub / 864;
        const int line = q1 & 15;
        const int tb   = q1 >> 4;
        const int bh = tb & 7, t = tb >> 3;
        const int pd = r % 12, cthw = r / 12;
        const int thw = cthw % 9, c = cthw / 9;
        const float* base = (t == 0 ? Q : (t == 1 ? Kt : V))
            + (size_t)((bh >> 1) * 64 + 32 + (bh & 1) * 8 + c) * D3;
        const int hh0 = (line >> 2) * 12 + (thw / 3) * 4;
        const int ww0 = (line & 3) * 12 + (thw % 3) * 4;
        const int dd0 = pd * 4;
        #pragma unroll
        for (int dh = 0; dh < 4; dh++) {
            const float* rowb = base + (size_t)(hh0 + dh) * D2 + ww0 * D + dd0;
            #pragma unroll
            for (int dw = 0; dw < 4; dw++) {
                float4 a = __ldg((const float4*)(rowb + dw * D));
                mx = fmaxf(mx, fmaxf(fmaxf(a.x, a.y), fmaxf(a.z, a.w)));
            }
        }
    } else {                              // br1: sw=2
        const int sub = idx - S3 - S2;
        const int r   = sub % 1728;
        const int q1  = sub / 1728;
        const int line = q1 & 63;
        const int tb   = q1 >> 6;
        const int bh = tb & 7, t = tb >> 3;
        const int pd = r % 24, cthw = r / 24;
        const int thw = cthw % 9, c = cthw / 9;
        const float* base = (t == 0 ? Q : (t == 1 ? Kt : V))
            + (size_t)((bh >> 1) * 64 + 16 + (bh & 1) * 8 + c) * D3;
        const int hh0 = (line >> 3) * 6 + (thw / 3) * 2;
        const int ww0 = (line & 7) * 6 + (thw % 3) * 2;
        const int dd0 = pd * 2;
        #pragma unroll
        for (int dh = 0; dh < 2; dh++) {
            const float* rowb = base + (size_t)(hh0 + dh) * D2 + ww0 * D + dd0;
            #pragma unroll
            for (int dw = 0; dw < 2; dw++) {
                float2 a = __ldg((const float2*)(rowb + dw * D));
                mx = fmaxf(mx, fmaxf(a.x, a.y));
            }
        }
    }
    g_pool[idx] = mx;
}

// ---------------------------------------------------------------------------
// Branch-specialized upsample: row-per-thread, factored trilinear.
// ---------------------------------------------------------------------------
template<int BR>
__device__ __forceinline__ void upsample(
    const float* __restrict__ sP, const int* __restrict__ sI0,
    const float* __restrict__ sF, float* __restrict__ out,
    int chbase, int h0, int w0, int split, int tid)
{
    constexpr int BW = 3 << BR;
    constexpr int NW = 16 >> BR;
    const size_t chD3 = (size_t)chbase * D3;

    if (BR == 0) {
        // identity: contiguous float4 copy of 72 rows x 48
        for (int i = tid; i < 72 * 12; i += 256) {
            const int row = i / 12, k = i - row * 12;
            const int c = row / 9, thw = row - c * 9;
            const int lh = thw / 3, lw = thw - lh * 3;
            float4 v = *(const float4*)(sP + row * 48 + k * 4);
            *(float4*)(out + chD3 + (size_t)c * D3
                       + (h0 + lh) * D2 + (w0 + lw) * D + k * 4) = v;
        }
        return;
    }

    constexpr int ROWS = 8 * BW * BW;
    constexpr int PER  = (BR == 3) ? (ROWS / 8) : ROWS;
    const int r0 = split * PER;

    for (int r = r0 + tid; r < r0 + PER; r += 256) {
        const int c   = r / (BW * BW);
        const int rem = r - c * (BW * BW);
        const int lh  = rem / BW;
        const int lw  = rem - lh * BW;

        const int   ih0 = sI0[lh], iw0 = sI0[lw];
        const int   ih1 = (ih0 < 2) ? ih0 + 1 : 2;
        const int   iw1 = (iw0 < 2) ? iw0 + 1 : 2;
        const float fh  = sF[lh],  fw  = sF[lw];

        const int cb  = c * 9;
        const int o00 = (cb + ih0 * 3 + iw0) * 48;
        const int o01 = (cb + ih0 * 3 + iw1) * 48;
        const int o10 = (cb + ih1 * 3 + iw0) * 48;
        const int o11 = (cb + ih1 * 3 + iw1) * 48;

        float* orow = out + chD3 + (size_t)c * D3 + (h0 + lh) * D2 + (w0 + lw) * D;

        #pragma unroll
        for (int wd = 0; wd < NW; wd++) {
            const int wd3 = wd * 3;
            float T[3];
            #pragma unroll
            for (int id = 0; id < 3; id++) {
                const float t00 = sP[o00 + wd3 + id], t01 = sP[o01 + wd3 + id];
                const float t10 = sP[o10 + wd3 + id], t11 = sP[o11 + wd3 + id];
                const float a0 = t00 + fw * (t01 - t00);
                const float a1 = t10 + fw * (t11 - t10);
                T[id] = a0 + fh * (a1 - a0);
            }
            float wbuf[BW];
            #pragma unroll
            for (int ld = 0; ld < BW; ld++) {
                const float pos = (float)ld * (2.0f / (float)(BW - 1));
                const int   id0 = (pos >= 2.0f) ? 2 : (int)pos;   // compile-time
                const float fd  = pos - (float)id0;
                const float lo = T[id0];
                const float hi = T[(id0 < 2) ? id0 + 1 : 2];
                wbuf[ld] = lo + fd * (hi - lo);
            }
            float* op = orow + wd * BW;
            if (BW == 6) {
                #pragma unroll
                for (int k = 0; k < 3; k++)
                    *(float2*)(op + k * 2) = make_float2(wbuf[k * 2], wbuf[k * 2 + 1]);
            } else {
                #pragma unroll
                for (int k = 0; k < BW / 4; k++)
                    *(float4*)(op + k * 4) =
                        make_float4(wbuf[k * 4], wbuf[k * 4 + 1],
                                    wbuf[k * 4 + 2], wbuf[k * 4 + 3]);
            }
        }
    }
}

// ---------------------------------------------------------------------------
// K2: attention + window-local trilinear upsample, fused.
// ---------------------------------------------------------------------------
__global__ __launch_bounds__(256) void attnK(
    const float* __restrict__ Q, const float* __restrict__ Kt,
    const float* __restrict__ V, const float* __restrict__ tab,
    float* __restrict__ out)
{
    __shared__ float sP[3 * 72 * 48];
    __shared__ float sTab[250];
    __shared__ int   sI0[24];
    __shared__ float sF[24];

    const int cid = blockIdx.x;
    int br, bh, wh, ww, line, split = 0;
    if (cid < 256) {
        br = 3; bh = cid >> 5;
        const int t5 = cid & 31;
        line = t5 >> 3; split = t5 & 7;
        wh = line >> 1; ww = line & 1;
    } else if (cid < 384) {
        br = 2; const int s = cid - 256;
        bh = s >> 4; line = s & 15;
        wh = line >> 2; ww = line & 3;
    } else if (cid < 896) {
        br = 1; const int s = cid - 384;
        bh = s >> 6; line = s & 63;
        wh = line >> 3; ww = line & 7;
    } else {
        br = 0; const int s = cid - 896;
        bh = s >> 8; line = s & 255;
        wh = line >> 4; ww = line & 15;
    }

    const int Nw  = 16 >> br;
    const int bw  = 3 << br;
    const int Ppd = 3 * Nw;
    const int tid = threadIdx.x;
    const int b = bh >> 1, head = bh & 1;
    const int chbase = b * 64 + br * 16 + head * 8;
    const int h0 = wh * bw, w0 = ww * bw;

    for (int i = tid; i < 250; i += 256) sTab[i] = tab[i];
    if (tid < bw) {
        const float pos = (float)tid * (2.0f / (float)(bw - 1));
        int i0 = (int)pos;
        if (i0 > 2) i0 = 2;
        sI0[tid] = i0;
        sF[tid]  = pos - (float)i0;
    }

    // ---- gather pooled tokens ----
    if (br == 0) {
        for (int e = tid; e < 3 * 72 * 48; e += 256) {
            const int pd = e % 48;
            const int r  = e / 48;
            const int thw = r % 9;
            const int c   = (r / 9) & 7;
            const int t   = r / 72;
            const float* base = (t == 0 ? Q : (t == 1 ? Kt : V))
                                + (size_t)(chbase + c) * D3;
            const int hh  = h0 + thw / 3;
            const int wwp = w0 + thw % 3;
            sP[(t * 72 + c * 9 + thw) * 48 + pd] =
                __ldg(base + (hh * D + wwp) * D + pd);
        }
    } else {
        const int per = 72 * Ppd;
        const int Nw2 = Nw * Nw;
        const int base_br = (br == 3) ? 0 : (br == 2 ? S3 : S3 + S2);
        for (int e = tid; e < 3 * per; e += 256) {
            const int t = e / per;
            const int r = e - t * per;
            const int cthw = r / Ppd;
            const int pd   = r - cthw * Ppd;
            sP[(t * 72 + cthw) * 48 + pd] =
                g_pool[base_br + ((size_t)(t * 8 + bh) * Nw2 + line) * per + r];
        }
    }
    __syncthreads();

    // ---- attention: warp per window along d; tokens written into q region ----
    const int warp = tid >> 5, lane = tid & 31;
    const float inv_scale = 0.3535533905932738f;
    const int m  = lane;
    const int mh = m / 9, mw = (m / 3) % 3, md = m % 3;

    for (int wd = warp; wd < Nw; wd += 8) {
        if (lane < 27) {
            const int wd3 = wd * 3;
            float q[8];
            #pragma unroll
            for (int c = 0; c < 8; c++)
                q[c] = sP[(c * 9 + mh * 3 + mw) * 48 + wd3 + md];

            float s[27];
            #pragma unroll
            for (int n = 0; n < 27; n++) {
                const int nh = n / 9, nw = (n / 3) % 3, nd = n % 3;
                float acc = 0.f;
                #pragma unroll
                for (int c = 0; c < 8; c++)
                    acc += q[c] * sP[((8 + c) * 9 + nh * 3 + nw) * 48 + wd3 + nd];
                s[n] = acc * inv_scale;
            }
            float mxv = s[0];
            #pragma unroll
            for (int n = 1; n < 27; n++) mxv = fmaxf(mxv, s[n]);
            float sum = 0.f;
            #pragma unroll
            for (int n = 0; n < 27; n++) { s[n] = __expf(s[n] - mxv); sum += s[n]; }
            const float inv = 1.0f / sum;
            #pragma unroll
            for (int n = 0; n < 27; n++) {
                const int nh = n / 9, nw = (n / 3) % 3, nd = n % 3;
                const int idx = ((mh - nh + 2) * 5 + (mw - nw + 2)) * 5 + (md - nd + 2);
                s[n] = s[n] * inv + sTab[idx * 2 + head];
            }
            #pragma unroll
            for (int c = 0; c < 8; c++) {
                float acc = 0.f;
                #pragma unroll
                for (int n = 0; n < 27; n++) {
                    const int nh = n / 9, nw = (n / 3) % 3, nd = n % 3;
                    acc += s[n] * sP[((16 + c) * 9 + nh * 3 + nw) * 48 + wd3 + nd];
                }
                sP[(c * 9 + mh * 3 + mw) * 48 + wd3 + md] = acc;
            }
        }
    }
    __syncthreads();

    // ---- branch-specialized upsample ----
    switch (br) {
        case 0: upsample<0>(sP, sI0, sF, out, chbase, h0, w0, split, tid); break;
        case 1: upsample<1>(sP, sI0, sF, out, chbase, h0, w0, split, tid); break;
        case 2: upsample<2>(sP, sI0, sF, out, chbase, h0, w0, split, tid); break;
        default: upsample<3>(sP, sI0, sF, out, chbase, h0, w0, split, tid); break;
    }
}

extern "C" void kernel_launch(void* const* d_in, const int* in_sizes, int n_in,
                              void* d_out, int out_size)
{
    const float* Q   = (const float*)d_in[0];
    const float* K   = (const float*)d_in[1];
    const float* V   = (const float*)d_in[2];
    const float* tab = (const float*)d_in[3];
    float* out = (float*)d_out;

    poolK<<<(TOTPOOL + 255) / 256, 256>>>(Q, K, V);
    attnK<<<2944, 256>>>(Q, K, V, tab, out);
}

// round 5
// speedup vs baseline: 2.6538x; 1.2813x over previous
#include <cuda_runtime.h>
#include <math.h>

#define D  48
#define D2 (48*48)
#define D3 (48*48*48)

// pooled-token scratch for branches 3,2,1 (thread-id-linear layout)
#define S3 41472
#define S2 331776
#define S1 2654208
#define TOTPOOL (S3+S2+S1)

__device__ float g_pool[TOTPOOL];

// ---------------------------------------------------------------------------
// K1: max-pool br1..3.  One thread per pooled element.
// ---------------------------------------------------------------------------
__global__ __launch_bounds__(256) void poolK(
    const float* __restrict__ Q, const float* __restrict__ Kt,
    const float* __restrict__ V)
{
    const int idx = blockIdx.x * 256 + threadIdx.x;
    if (idx >= TOTPOOL) return;

    float mx = -1e30f;

    if (idx < S3) {                       // br3: sw=8
        const int sub = idx;
        const int r   = sub % 432;
        const int q1  = sub / 432;
        const int line = q1 & 3;
        const int tb   = q1 >> 2;
        const int bh = tb & 7, t = tb >> 3;
        const int pd = r % 6, cthw = r / 6;
        const int thw = cthw % 9, c = cthw / 9;
        const float* base = (t == 0 ? Q : (t == 1 ? Kt : V))
            + (size_t)((bh >> 1) * 64 + 48 + (bh & 1) * 8 + c) * D3;
        const int hh0 = (line >> 1) * 24 + (thw / 3) * 8;
        const int ww0 = (line & 1) * 24 + (thw % 3) * 8;
        const int dd0 = pd * 8;
        for (int dh = 0; dh < 8; dh++) {
            const float* rowb = base + (size_t)(hh0 + dh) * D2 + ww0 * D + dd0;
            #pragma unroll
            for (int dw = 0; dw < 8; dw++) {
                float4 a = __ldg((const float4*)(rowb + dw * D));
                float4 b = __ldg((const float4*)(rowb + dw * D + 4));
                mx = fmaxf(mx, fmaxf(fmaxf(a.x, a.y), fmaxf(a.z, a.w)));
                mx = fmaxf(mx, fmaxf(fmaxf(b.x, b.y), fmaxf(b.z, b.w)));
            }
        }
    } else if (idx < S3 + S2) {           // br2: sw=4
        const int sub = idx - S3;
        const int r   = sub % 864;
        const int q1  = sub / 864;
        const int line = q1 & 15;
        const int tb   = q1 >> 4;
        const int bh = tb & 7, t = tb >> 3;
        const int pd = r % 12, cthw = r / 12;
        const int thw = cthw % 9, c = cthw / 9;
        const float* base = (t == 0 ? Q : (t == 1 ? Kt : V))
            + (size_t)((bh >> 1) * 64 + 32 + (bh & 1) * 8 + c) * D3;
        const int hh0 = (line >> 2) * 12 + (thw / 3) * 4;
        const int ww0 = (line & 3) * 12 + (thw % 3) * 4;
        const int dd0 = pd * 4;
        #pragma unroll
        for (int dh = 0; dh < 4; dh++) {
            const float* rowb = base + (size_t)(hh0 + dh) * D2 + ww0 * D + dd0;
            #pragma unroll
            for (int dw = 0; dw < 4; dw++) {
                float4 a = __ldg((const float4*)(rowb + dw * D));
                mx = fmaxf(mx, fmaxf(fmaxf(a.x, a.y), fmaxf(a.z, a.w)));
            }
        }
    } else {                              // br1: sw=2
        const int sub = idx - S3 - S2;
        const int r   = sub % 1728;
        const int q1  = sub / 1728;
        const int line = q1 & 63;
        const int tb   = q1 >> 6;
        const int bh = tb & 7, t = tb >> 3;
        const int pd = r % 24, cthw = r / 24;
        const int thw = cthw % 9, c = cthw / 9;
        const float* base = (t == 0 ? Q : (t == 1 ? Kt : V))
            + (size_t)((bh >> 1) * 64 + 16 + (bh & 1) * 8 + c) * D3;
        const int hh0 = (line >> 3) * 6 + (thw / 3) * 2;
        const int ww0 = (line & 7) * 6 + (thw % 3) * 2;
        const int dd0 = pd * 2;
        #pragma unroll
        for (int dh = 0; dh < 2; dh++) {
            const float* rowb = base + (size_t)(hh0 + dh) * D2 + ww0 * D + dd0;
            #pragma unroll
            for (int dw = 0; dw < 2; dw++) {
                float2 a = __ldg((const float2*)(rowb + dw * D));
                mx = fmaxf(mx, fmaxf(a.x, a.y));
            }
        }
    }
    g_pool[idx] = mx;
}

// ---------------------------------------------------------------------------
// Branch-specialized upsample: row-per-thread, factored trilinear.
// ---------------------------------------------------------------------------
template<int BR>
__device__ __forceinline__ void upsample(
    const float* __restrict__ sP, const int* __restrict__ sI0,
    const float* __restrict__ sF, float* __restrict__ out,
    int chbase, int h0, int w0, int split, int tid)
{
    constexpr int BW = 3 << BR;
    constexpr int NW = 16 >> BR;
    const size_t chD3 = (size_t)chbase * D3;

    if (BR == 0) {
        for (int i = tid; i < 72 * 12; i += 256) {
            const int row = i / 12, k = i - row * 12;
            const int c = row / 9, thw = row - c * 9;
            const int lh = thw / 3, lw = thw - lh * 3;
            float4 v = *(const float4*)(sP + row * 48 + k * 4);
            *(float4*)(out + chD3 + (size_t)c * D3
                       + (h0 + lh) * D2 + (w0 + lw) * D + k * 4) = v;
        }
        return;
    }

    constexpr int ROWS = 8 * BW * BW;
    constexpr int PER  = (BR == 3) ? (ROWS / 8) : ROWS;
    const int r0 = split * PER;

    for (int r = r0 + tid; r < r0 + PER; r += 256) {
        const int c   = r / (BW * BW);
        const int rem = r - c * (BW * BW);
        const int lh  = rem / BW;
        const int lw  = rem - lh * BW;

        const int   ih0 = sI0[lh], iw0 = sI0[lw];
        const int   ih1 = (ih0 < 2) ? ih0 + 1 : 2;
        const int   iw1 = (iw0 < 2) ? iw0 + 1 : 2;
        const float fh  = sF[lh],  fw  = sF[lw];

        const int cb  = c * 9;
        const int o00 = (cb + ih0 * 3 + iw0) * 48;
        const int o01 = (cb + ih0 * 3 + iw1) * 48;
        const int o10 = (cb + ih1 * 3 + iw0) * 48;
        const int o11 = (cb + ih1 * 3 + iw1) * 48;

        float* orow = out + chD3 + (size_t)c * D3 + (h0 + lh) * D2 + (w0 + lw) * D;

        #pragma unroll
        for (int wd = 0; wd < NW; wd++) {
            const int wd3 = wd * 3;
            float T[3];
            #pragma unroll
            for (int id = 0; id < 3; id++) {
                const float t00 = sP[o00 + wd3 + id], t01 = sP[o01 + wd3 + id];
                const float t10 = sP[o10 + wd3 + id], t11 = sP[o11 + wd3 + id];
                const float a0 = t00 + fw * (t01 - t00);
                const float a1 = t10 + fw * (t11 - t10);
                T[id] = a0 + fh * (a1 - a0);
            }
            float wbuf[BW];
            #pragma unroll
            for (int ld = 0; ld < BW; ld++) {
                const float pos = (float)ld * (2.0f / (float)(BW - 1));
                const int   id0 = (pos >= 2.0f) ? 2 : (int)pos;
                const float fd  = pos - (float)id0;
                const float lo = T[id0];
                const float hi = T[(id0 < 2) ? id0 + 1 : 2];
                wbuf[ld] = lo + fd * (hi - lo);
            }
            float* op = orow + wd * BW;
            if (BW == 6) {
                #pragma unroll
                for (int k = 0; k < 3; k++)
                    *(float2*)(op + k * 2) = make_float2(wbuf[k * 2], wbuf[k * 2 + 1]);
            } else {
                #pragma unroll
                for (int k = 0; k < BW / 4; k++)
                    *(float4*)(op + k * 4) =
                        make_float4(wbuf[k * 4], wbuf[k * 4 + 1],
                                    wbuf[k * 4 + 2], wbuf[k * 4 + 3]);
            }
        }
    }
}

// ---------------------------------------------------------------------------
// K2: attention + window-local trilinear upsample, fused.
// ---------------------------------------------------------------------------
__global__ __launch_bounds__(256) void attnK(
    const float* __restrict__ Q, const float* __restrict__ Kt,
    const float* __restrict__ V, const float* __restrict__ tab,
    float* __restrict__ out)
{
    __shared__ float sP[3 * 72 * 48];
    __shared__ float sTabH[125];          // head-sliced rpb table
    __shared__ int   sI0[24];
    __shared__ float sF[24];

    const int cid = blockIdx.x;
    int br, bh, wh, ww, line, split = 0;
    if (cid < 256) {
        br = 3; bh = cid >> 5;
        const int t5 = cid & 31;
        line = t5 >> 3; split = t5 & 7;
        wh = line >> 1; ww = line & 1;
    } else if (cid < 384) {
        br = 2; const int s = cid - 256;
        bh = s >> 4; line = s & 15;
        wh = line >> 2; ww = line & 3;
    } else if (cid < 896) {
        br = 1; const int s = cid - 384;
        bh = s >> 6; line = s & 63;
        wh = line >> 3; ww = line & 7;
    } else {
        br = 0; const int s = cid - 896;
        bh = s >> 8; line = s & 255;
        wh = line >> 4; ww = line & 15;
    }

    const int Nw  = 16 >> br;
    const int bw  = 3 << br;
    const int Ppd = 3 * Nw;
    const int tid = threadIdx.x;
    const int b = bh >> 1, head = bh & 1;
    const int chbase = b * 64 + br * 16 + head * 8;
    const int h0 = wh * bw, w0 = ww * bw;

    if (tid < 125) sTabH[tid] = __ldg(tab + tid * 2 + head);
    if (tid >= 128 && tid - 128 < bw) {
        const int u = tid - 128;
        const float pos = (float)u * (2.0f / (float)(bw - 1));
        int i0 = (int)pos;
        if (i0 > 2) i0 = 2;
        sI0[u] = i0;
        sF[u]  = pos - (float)i0;
    }

    // ---- gather pooled tokens (vectorized) ----
    if (br == 0) {
        // identity: float4 over pd
        for (int e = tid; e < 3 * 72 * 12; e += 256) {
            const int k = e % 12;
            const int r = e / 12;
            const int thw = r % 9;
            const int c   = (r / 9) & 7;
            const int t   = r / 72;
            const float* base = (t == 0 ? Q : (t == 1 ? Kt : V))
                                + (size_t)(chbase + c) * D3;
            const int hh  = h0 + thw / 3;
            const int wwp = w0 + thw % 3;
            float4 v = __ldg((const float4*)(base + (hh * D + wwp) * D + k * 4));
            *(float4*)(sP + r * 48 + k * 4) = v;
        }
    } else {
        const int per  = 72 * Ppd;
        const int Nw2  = Nw * Nw;
        const int base_br = (br == 3) ? 0 : (br == 2 ? S3 : S3 + S2);
        if (br == 3) {                    // Ppd=6 -> float2
            const int units = per / 2;    // 216
            for (int e = tid; e < 3 * units; e += 256) {
                const int t = e / units;
                const int u = e - t * units;
                const int cthw = u / 3, k = u - cthw * 3;
                const float2 v = *(const float2*)(g_pool + base_br
                    + ((size_t)(t * 8 + bh) * Nw2 + line) * per + u * 2);
                *(float2*)(sP + (t * 72 + cthw) * 48 + k * 2) = v;
            }
        } else {                          // Ppd=12/24 -> float4
            const int pk = Ppd / 4;
            const int units = per / 4;
            for (int e = tid; e < 3 * units; e += 256) {
                const int t = e / units;
                const int u = e - t * units;
                const int cthw = u / pk, k = u - cthw * pk;
                const float4 v = *(const float4*)(g_pool + base_br
                    + ((size_t)(t * 8 + bh) * Nw2 + line) * per + u * 4);
                *(float4*)(sP + (t * 72 + cthw) * 48 + k * 4) = v;
            }
        }
    }
    __syncthreads();

    // ---- attention: warp per window along d ----
    const int warp = tid >> 5, lane = tid & 31;
    const float inv_scale = 0.3535533905932738f;
    const int m  = lane;
    const int mh = m / 9, mw = (m / 3) % 3, md = m % 3;
    const int mbase = mh * 25 + mw * 5 + md + 62;   // bias row base (+62 folded)

    for (int wd = warp; wd < Nw; wd += 8) {
        if (lane < 27) {
            const int wd3 = wd * 3;
            const float* qb = sP + (mh * 3 + mw) * 48 + wd3 + md;
            float q[8];
            #pragma unroll
            for (int c = 0; c < 8; c++) q[c] = qb[c * 432];

            float s[27];
            #pragma unroll
            for (int n = 0; n < 27; n++) {
                const int nh = n / 9, nw = (n / 3) % 3, nd = n % 3;
                const float* kb = sP + (72 + nh * 3 + nw) * 48 + wd3 + nd;
                float acc = 0.f;
                #pragma unroll
                for (int c = 0; c < 8; c++) acc += q[c] * kb[c * 432];
                s[n] = acc * inv_scale;
            }
            float mxv = s[0];
            #pragma unroll
            for (int n = 1; n < 27; n++) mxv = fmaxf(mxv, s[n]);
            float sum = 0.f;
            #pragma unroll
            for (int n = 0; n < 27; n++) { s[n] = __expf(s[n] - mxv); sum += s[n]; }
            const float inv = 1.0f / sum;
            #pragma unroll
            for (int n = 0; n < 27; n++) {
                const int nh = n / 9, nw = (n / 3) % 3, nd = n % 3;
                s[n] = s[n] * inv + sTabH[mbase - (nh * 25 + nw * 5 + nd)];
            }
            float av[8];
            #pragma unroll
            for (int c = 0; c < 8; c++) av[c] = 0.f;
            #pragma unroll
            for (int n = 0; n < 27; n++) {
                const int nh = n / 9, nw = (n / 3) % 3, nd = n % 3;
                const float* vb = sP + (144 + nh * 3 + nw) * 48 + wd3 + nd;
                const float sn = s[n];
                #pragma unroll
                for (int c = 0; c < 8; c++) av[c] += sn * vb[c * 432];
            }
            float* ob = sP + (mh * 3 + mw) * 48 + wd3 + md;
            #pragma unroll
            for (int c = 0; c < 8; c++) ob[c * 432] = av[c];
        }
    }
    __syncthreads();

    // ---- branch-specialized upsample ----
    switch (br) {
        case 0: upsample<0>(sP, sI0, sF, out, chbase, h0, w0, split, tid); break;
        case 1: upsample<1>(sP, sI0, sF, out, chbase, h0, w0, split, tid); break;
        case 2: upsample<2>(sP, sI0, sF, out, chbase, h0, w0, split, tid); break;
        default: upsample<3>(sP, sI0, sF, out, chbase, h0, w0, split, tid); break;
    }
}

extern "C" void kernel_launch(void* const* d_in, const int* in_sizes, int n_in,
                              void* d_out, int out_size)
{
    const float* Q   = (const float*)d_in[0];
    const float* K   = (const float*)d_in[1];
    const float* V   = (const float*)d_in[2];
    const float* tab = (const float*)d_in[3];
    float* out = (float*)d_out;

    poolK<<<(TOTPOOL + 255) / 256, 256>>>(Q, K, V);
    attnK<<<2944, 256>>>(Q, K, V, tab, out);
}

// round 6
// speedup vs baseline: 2.7458x; 1.0347x over previous
#include <cuda_runtime.h>
#include <math.h>

#define D  48
#define D2 (48*48)
#define D3 (48*48*48)

#define S3 41472
#define S2 331776
#define S1 2654208
#define TOTPOOL (S3+S2+S1)

#define TSTRIDE 392           // padded token-row stride (floats), 16B aligned

__device__ float g_pool[TOTPOOL];

// ---------------------------------------------------------------------------
// K1: max-pool br1..3.  One thread per pooled element. (unchanged)
// ---------------------------------------------------------------------------
__global__ __launch_bounds__(256) void poolK(
    const float* __restrict__ Q, const float* __restrict__ Kt,
    const float* __restrict__ V)
{
    const int idx = blockIdx.x * 256 + threadIdx.x;
    if (idx >= TOTPOOL) return;

    float mx = -1e30f;

    if (idx < S3) {                       // br3: sw=8
        const int sub = idx;
        const int r   = sub % 432;
        const int q1  = sub / 432;
        const int line = q1 & 3;
        const int tb   = q1 >> 2;
        const int bh = tb & 7, t = tb >> 3;
        const int pd = r % 6, cthw = r / 6;
        const int thw = cthw % 9, c = cthw / 9;
        const float* base = (t == 0 ? Q : (t == 1 ? Kt : V))
            + (size_t)((bh >> 1) * 64 + 48 + (bh & 1) * 8 + c) * D3;
        const int hh0 = (line >> 1) * 24 + (thw / 3) * 8;
        const int ww0 = (line & 1) * 24 + (thw % 3) * 8;
        const int dd0 = pd * 8;
        for (int dh = 0; dh < 8; dh++) {
            const float* rowb = base + (size_t)(hh0 + dh) * D2 + ww0 * D + dd0;
            #pragma unroll
            for (int dw = 0; dw < 8; dw++) {
                float4 a = __ldg((const float4*)(rowb + dw * D));
                float4 b = __ldg((const float4*)(rowb + dw * D + 4));
                mx = fmaxf(mx, fmaxf(fmaxf(a.x, a.y), fmaxf(a.z, a.w)));
                mx = fmaxf(mx, fmaxf(fmaxf(b.x, b.y), fmaxf(b.z, b.w)));
            }
        }
    } else if (idx < S3 + S2) {           // br2: sw=4
        const int sub = idx - S3;
        const int r   = sub % 864;
        const int q1  = sub / 864;
        const int line = q1 & 15;
        const int tb   = q1 >> 4;
        const int bh = tb & 7, t = tb >> 3;
        const int pd = r % 12, cthw = r / 12;
        const int thw = cthw % 9, c = cthw / 9;
        const float* base = (t == 0 ? Q : (t == 1 ? Kt : V))
            + (size_t)((bh >> 1) * 64 + 32 + (bh & 1) * 8 + c) * D3;
        const int hh0 = (line >> 2) * 12 + (thw / 3) * 4;
        const int ww0 = (line & 3) * 12 + (thw % 3) * 4;
        const int dd0 = pd * 4;
        #pragma unroll
        for (int dh = 0; dh < 4; dh++) {
            const float* rowb = base + (size_t)(hh0 + dh) * D2 + ww0 * D + dd0;
            #pragma unroll
            for (int dw = 0; dw < 4; dw++) {
                float4 a = __ldg((const float4*)(rowb + dw * D));
                mx = fmaxf(mx, fmaxf(fmaxf(a.x, a.y), fmaxf(a.z, a.w)));
            }
        }
    } else {                              // br1: sw=2
        const int sub = idx - S3 - S2;
        const int r   = sub % 1728;
        const int q1  = sub / 1728;
        const int line = q1 & 63;
        const int tb   = q1 >> 6;
        const int bh = tb & 7, t = tb >> 3;
        const int pd = r % 24, cthw = r / 24;
        const int thw = cthw % 9, c = cthw / 9;
        const float* base = (t == 0 ? Q : (t == 1 ? Kt : V))
            + (size_t)((bh >> 1) * 64 + 16 + (bh & 1) * 8 + c) * D3;
        const int hh0 = (line >> 3) * 6 + (thw / 3) * 2;
        const int ww0 = (line & 7) * 6 + (thw % 3) * 2;
        const int dd0 = pd * 2;
        #pragma unroll
        for (int dh = 0; dh < 2; dh++) {
            const float* rowb = base + (size_t)(hh0 + dh) * D2 + ww0 * D + dd0;
            #pragma unroll
            for (int dw = 0; dw < 2; dw++) {
                float2 a = __ldg((const float2*)(rowb + dw * D));
                mx = fmaxf(mx, fmaxf(a.x, a.y));
            }
        }
    }
    g_pool[idx] = mx;
}

// ---------------------------------------------------------------------------
// Upsample (br>=1): row-per-thread factored trilinear, c-innermost layout.
// ---------------------------------------------------------------------------
template<int BR>
__device__ __forceinline__ void upsample(
    const float* __restrict__ sP, const int* __restrict__ sI0,
    const float* __restrict__ sF, float* __restrict__ out,
    int chbase, int h0, int w0, int split, int tid)
{
    constexpr int BW = 3 << BR;
    constexpr int NW = 16 >> BR;
    const size_t chD3 = (size_t)chbase * D3;

    constexpr int ROWS = 8 * BW * BW;
    constexpr int PER  = (BR == 3) ? (ROWS / 8) : ROWS;
    const int r0 = split * PER;

    for (int r = r0 + tid; r < r0 + PER; r += 256) {
        const int c   = r / (BW * BW);
        const int rem = r - c * (BW * BW);
        const int lh  = rem / BW;
        const int lw  = rem - lh * BW;

        const int   ih0 = sI0[lh], iw0 = sI0[lw];
        const int   ih1 = (ih0 < 2) ? ih0 + 1 : 2;
        const int   iw1 = (iw0 < 2) ? iw0 + 1 : 2;
        const float fh  = sF[lh],  fw  = sF[lw];

        const int o00 = (ih0 * 3 + iw0) * TSTRIDE + c;
        const int o01 = (ih0 * 3 + iw1) * TSTRIDE + c;
        const int o10 = (ih1 * 3 + iw0) * TSTRIDE + c;
        const int o11 = (ih1 * 3 + iw1) * TSTRIDE + c;

        float* orow = out + chD3 + (size_t)c * D3 + (h0 + lh) * D2 + (w0 + lw) * D;

        #pragma unroll
        for (int wd = 0; wd < NW; wd++) {
            const int wd3 = wd * 3;
            float T[3];
            #pragma unroll
            for (int id = 0; id < 3; id++) {
                const int po = (wd3 + id) * 8;
                const float t00 = sP[o00 + po], t01 = sP[o01 + po];
                const float t10 = sP[o10 + po], t11 = sP[o11 + po];
                const float a0 = t00 + fw * (t01 - t00);
                const float a1 = t10 + fw * (t11 - t10);
                T[id] = a0 + fh * (a1 - a0);
            }
            float wbuf[BW];
            #pragma unroll
            for (int ld = 0; ld < BW; ld++) {
                const float pos = (float)ld * (2.0f / (float)(BW - 1));
                const int   id0 = (pos >= 2.0f) ? 2 : (int)pos;
                const float fd  = pos - (float)id0;
                const float lo = T[id0];
                const float hi = T[(id0 < 2) ? id0 + 1 : 2];
                wbuf[ld] = lo + fd * (hi - lo);
            }
            float* op = orow + wd * BW;
            if (BW == 6) {
                #pragma unroll
                for (int k = 0; k < 3; k++)
                    *(float2*)(op + k * 2) = make_float2(wbuf[k * 2], wbuf[k * 2 + 1]);
            } else {
                #pragma unroll
                for (int k = 0; k < BW / 4; k++)
                    *(float4*)(op + k * 4) =
                        make_float4(wbuf[k * 4], wbuf[k * 4 + 1],
                                    wbuf[k * 4 + 2], wbuf[k * 4 + 3]);
            }
        }
    }
}

// ---------------------------------------------------------------------------
// K2: attention + window-local upsample, c-innermost smem layout.
// ---------------------------------------------------------------------------
__global__ __launch_bounds__(256) void attnK(
    const float* __restrict__ Q, const float* __restrict__ Kt,
    const float* __restrict__ V, const float* __restrict__ tab,
    float* __restrict__ out)
{
    __shared__ float sP[3 * 9 * TSTRIDE];    // 42336 B
    __shared__ float sTabH[125];
    __shared__ int   sI0[24];
    __shared__ float sF[24];

    const int cid = blockIdx.x;
    int br, bh, wh, ww, line, split = 0;
    if (cid < 256) {
        br = 3; bh = cid >> 5;
        const int t5 = cid & 31;
        line = t5 >> 3; split = t5 & 7;
        wh = line >> 1; ww = line & 1;
    } else if (cid < 384) {
        br = 2; const int s = cid - 256;
        bh = s >> 4; line = s & 15;
        wh = line >> 2; ww = line & 3;
    } else if (cid < 896) {
        br = 1; const int s = cid - 384;
        bh = s >> 6; line = s & 63;
        wh = line >> 3; ww = line & 7;
    } else {
        br = 0; const int s = cid - 896;
        bh = s >> 8; line = s & 255;
        wh = line >> 4; ww = line & 15;
    }

    const int Nw  = 16 >> br;
    const int bw  = 3 << br;
    const int tid = threadIdx.x;
    const int b = bh >> 1, head = bh & 1;
    const int chbase = b * 64 + br * 16 + head * 8;
    const int h0 = wh * bw, w0 = ww * bw;

    if (tid < 125) sTabH[tid] = __ldg(tab + tid * 2 + head);
    if (tid >= 128 && tid - 128 < bw) {
        const int u = tid - 128;
        const float pos = (float)u * (2.0f / (float)(bw - 1));
        int i0 = (int)pos;
        if (i0 > 2) i0 = 2;
        sI0[u] = i0;
        sF[u]  = pos - (float)i0;
    }

    // ---- gather pooled tokens into c-innermost layout ----
    if (br == 0) {
        for (int e = tid; e < 2592; e += 256) {           // 3t*9tok*12q*8c
            const int c    = e & 7;
            const int rest = e >> 3;                      // 0..323
            const int pdq  = rest % 12;
            const int r2   = rest / 12;                   // 0..26
            const int token = r2 % 9;
            const int t     = r2 / 9;
            const float* base = (t == 0 ? Q : (t == 1 ? Kt : V))
                + (size_t)(chbase + c) * D3
                + (h0 + token / 3) * D2 + (w0 + token % 3) * D + 4 * pdq;
            float4 v = __ldg((const float4*)base);
            float* dst = sP + (t * 9 + token) * TSTRIDE + pdq * 32 + c;
            dst[0] = v.x; dst[8] = v.y; dst[16] = v.z; dst[24] = v.w;
        }
    } else if (br < 3) {
        const int Ppd = 3 * Nw;                           // 24 or 12
        const int pk  = Ppd >> 2;                         // 6 or 3
        const int per = 72 * Ppd;
        const int Nw2 = Nw * Nw;
        const int base_br = (br == 2) ? S3 : S3 + S2;
        const int tot = 3 * 9 * pk * 8;
        for (int e = tid; e < tot; e += 256) {
            const int c    = e & 7;
            const int rest = e >> 3;
            const int pdq  = rest % pk;
            const int r2   = rest / pk;
            const int token = r2 % 9;
            const int t     = r2 / 9;
            const float4 v = *(const float4*)(g_pool + base_br
                + ((size_t)(t * 8 + bh) * Nw2 + line) * per
                + (c * 9 + token) * Ppd + 4 * pdq);
            float* dst = sP + (t * 9 + token) * TSTRIDE + pdq * 32 + c;
            dst[0] = v.x; dst[8] = v.y; dst[16] = v.z; dst[24] = v.w;
        }
    } else {                                              // br3: Ppd=6, float2
        for (int e = tid; e < 648; e += 256) {            // 3*9*3*8
            const int c    = e & 7;
            const int rest = e >> 3;
            const int pdp  = rest % 3;
            const int r2   = rest / 3;
            const int token = r2 % 9;
            const int t     = r2 / 9;
            const float2 v = *(const float2*)(g_pool
                + ((size_t)(t * 8 + bh) * 4 + line) * 432
                + (c * 9 + token) * 6 + 2 * pdp);
            float* dst = sP + (t * 9 + token) * TSTRIDE + pdp * 16 + c;
            dst[0] = v.x; dst[8] = v.y;
        }
    }
    __syncthreads();

    // ---- attention: warp per window along d (vectorized over c) ----
    const int warp = tid >> 5, lane = tid & 31;
    const float inv_scale = 0.3535533905932738f;
    const int m  = lane;
    const int mh = m / 9, mw = (m / 3) % 3, md = m % 3;
    const int tq = mh * 3 + mw;
    const int mbase = mh * 25 + mw * 5 + md + 62;

    for (int wd = warp; wd < Nw; wd += 8) {
        if (lane < 27) {
            const int pdm = wd * 3 + md;
            float* qp = sP + tq * TSTRIDE + pdm * 8;
            const float4 q0 = *(const float4*)qp;
            const float4 q1 = *(const float4*)(qp + 4);

            float s[27];
            #pragma unroll
            for (int n = 0; n < 27; n++) {
                const int tn = n / 3;                     // nh*3+nw
                const int nd = n % 3;
                const float* kp = sP + (9 + tn) * TSTRIDE + (wd * 3 + nd) * 8;
                const float4 k0 = *(const float4*)kp;
                const float4 k1 = *(const float4*)(kp + 4);
                float acc = q0.x * k0.x + q0.y * k0.y + q0.z * k0.z + q0.w * k0.w
                          + q1.x * k1.x + q1.y * k1.y + q1.z * k1.z + q1.w * k1.w;
                s[n] = acc * inv_scale;
            }
            float mxv = s[0];
            #pragma unroll
            for (int n = 1; n < 27; n++) mxv = fmaxf(mxv, s[n]);
            float sum = 0.f;
            #pragma unroll
            for (int n = 0; n < 27; n++) { s[n] = __expf(s[n] - mxv); sum += s[n]; }
            const float inv = 1.0f / sum;
            #pragma unroll
            for (int n = 0; n < 27; n++) {
                const int nh = n / 9, nw = (n / 3) % 3, nd = n % 3;
                s[n] = s[n] * inv + sTabH[mbase - (nh * 25 + nw * 5 + nd)];
            }
            float4 a0 = make_float4(0.f, 0.f, 0.f, 0.f);
            float4 a1 = make_float4(0.f, 0.f, 0.f, 0.f);
            #pragma unroll
            for (int n = 0; n < 27; n++) {
                const int tn = n / 3;
                const int nd = n % 3;
                const float* vp = sP + (18 + tn) * TSTRIDE + (wd * 3 + nd) * 8;
                const float4 v0 = *(const float4*)vp;
                const float4 v1 = *(const float4*)(vp + 4);
                const float sn = s[n];
                a0.x += sn * v0.x; a0.y += sn * v0.y;
                a0.z += sn * v0.z; a0.w += sn * v0.w;
                a1.x += sn * v1.x; a1.y += sn * v1.y;
                a1.z += sn * v1.z; a1.w += sn * v1.w;
            }
            *(float4*)qp       = a0;
            *(float4*)(qp + 4) = a1;
        }
    }
    __syncthreads();

    // ---- scatter ----
    if (br == 0) {
        // identity: repack c-innermost -> pd-contiguous gmem
        const size_t chD3 = (size_t)chbase * D3;
        for (int e = tid; e < 864; e += 256) {            // 9tok*12q*8c
            const int c    = e & 7;
            const int rest = e >> 3;
            const int pdq  = rest % 12;
            const int token = rest / 12;
            const float* src = sP + token * TSTRIDE + pdq * 32 + c;
            float4 v = make_float4(src[0], src[8], src[16], src[24]);
            *(float4*)(out + chD3 + (size_t)c * D3
                       + (h0 + token / 3) * D2 + (w0 + token % 3) * D + 4 * pdq) = v;
        }
    } else if (br == 1) {
        upsample<1>(sP, sI0, sF, out, chbase, h0, w0, split, tid);
    } else if (br == 2) {
        upsample<2>(sP, sI0, sF, out, chbase, h0, w0, split, tid);
    } else {
        upsample<3>(sP, sI0, sF, out, chbase, h0, w0, split, tid);
    }
}

extern "C" void kernel_launch(void* const* d_in, const int* in_sizes, int n_in,
                              void* d_out, int out_size)
{
    const float* Q   = (const float*)d_in[0];
    const float* K   = (const float*)d_in[1];
    const float* V   = (const float*)d_in[2];
    const float* tab = (const float*)d_in[3];
    float* out = (float*)d_out;

    poolK<<<(TOTPOOL + 255) / 256, 256>>>(Q, K, V);
    attnK<<<2944, 256>>>(Q, K, V, tab, out);
}

// round 7
// speedup vs baseline: 2.8028x; 1.0208x over previous
#include <cuda_runtime.h>
#include <math.h>

#define D  48
#define D2 (48*48)
#define D3 (48*48*48)

#define S3 41472
#define S2 331776
#define S1 2654208
#define TOTPOOL (S3+S2+S1)
#define POOL_CTAS (TOTPOOL/256)      // 11826 exactly

#define TS 200                        // token-row stride (floats): 24pd*8c=192, pad 8

__device__ float g_pool[TOTPOOL];

// ---------------------------------------------------------------------------
// pooling work for one element (idx in g_pool)
// ---------------------------------------------------------------------------
__device__ __forceinline__ void pool_one(
    int idx, const float* __restrict__ Q, const float* __restrict__ Kt,
    const float* __restrict__ V)
{
    float mx = -1e30f;
    if (idx < S3) {                       // br3: sw=8
        const int r   = idx % 432;
        const int q1  = idx / 432;
        const int line = q1 & 3;
        const int tb   = q1 >> 2;
        const int bh = tb & 7, t = tb >> 3;
        const int pd = r % 6, cthw = r / 6;
        const int thw = cthw % 9, c = cthw / 9;
        const float* base = (t == 0 ? Q : (t == 1 ? Kt : V))
            + (size_t)((bh >> 1) * 64 + 48 + (bh & 1) * 8 + c) * D3;
        const int hh0 = (line >> 1) * 24 + (thw / 3) * 8;
        const int ww0 = (line & 1) * 24 + (thw % 3) * 8;
        const int dd0 = pd * 8;
        for (int dh = 0; dh < 8; dh++) {
            const float* rowb = base + (size_t)(hh0 + dh) * D2 + ww0 * D + dd0;
            #pragma unroll
            for (int dw = 0; dw < 8; dw++) {
                float4 a = __ldg((const float4*)(rowb + dw * D));
                float4 b = __ldg((const float4*)(rowb + dw * D + 4));
                mx = fmaxf(mx, fmaxf(fmaxf(a.x, a.y), fmaxf(a.z, a.w)));
                mx = fmaxf(mx, fmaxf(fmaxf(b.x, b.y), fmaxf(b.z, b.w)));
            }
        }
    } else if (idx < S3 + S2) {           // br2: sw=4
        const int sub = idx - S3;
        const int r   = sub % 864;
        const int q1  = sub / 864;
        const int line = q1 & 15;
        const int tb   = q1 >> 4;
        const int bh = tb & 7, t = tb >> 3;
        const int pd = r % 12, cthw = r / 12;
        const int thw = cthw % 9, c = cthw / 9;
        const float* base = (t == 0 ? Q : (t == 1 ? Kt : V))
            + (size_t)((bh >> 1) * 64 + 32 + (bh & 1) * 8 + c) * D3;
        const int hh0 = (line >> 2) * 12 + (thw / 3) * 4;
        const int ww0 = (line & 3) * 12 + (thw % 3) * 4;
        const int dd0 = pd * 4;
        #pragma unroll
        for (int dh = 0; dh < 4; dh++) {
            const float* rowb = base + (size_t)(hh0 + dh) * D2 + ww0 * D + dd0;
            #pragma unroll
            for (int dw = 0; dw < 4; dw++) {
                float4 a = __ldg((const float4*)(rowb + dw * D));
                mx = fmaxf(mx, fmaxf(fmaxf(a.x, a.y), fmaxf(a.z, a.w)));
            }
        }
    } else {                              // br1: sw=2
        const int sub = idx - S3 - S2;
        const int r   = sub % 1728;
        const int q1  = sub / 1728;
        const int line = q1 & 63;
        const int tb   = q1 >> 6;
        const int bh = tb & 7, t = tb >> 3;
        const int pd = r % 24, cthw = r / 24;
        const int thw = cthw % 9, c = cthw / 9;
        const float* base = (t == 0 ? Q : (t == 1 ? Kt : V))
            + (size_t)((bh >> 1) * 64 + 16 + (bh & 1) * 8 + c) * D3;
        const int hh0 = (line >> 3) * 6 + (thw / 3) * 2;
        const int ww0 = (line & 7) * 6 + (thw % 3) * 2;
        const int dd0 = pd * 2;
        #pragma unroll
        for (int dh = 0; dh < 2; dh++) {
            const float* rowb = base + (size_t)(hh0 + dh) * D2 + ww0 * D + dd0;
            #pragma unroll
            for (int dw = 0; dw < 2; dw++) {
                float2 a = __ldg((const float2*)(rowb + dw * D));
                mx = fmaxf(mx, fmaxf(a.x, a.y));
            }
        }
    }
    g_pool[idx] = mx;
}

// ---------------------------------------------------------------------------
// attention core: warp-per-window, c-innermost smem, windows [0, NwLoc)
// ---------------------------------------------------------------------------
__device__ __forceinline__ void attn_core(
    float* __restrict__ sP, const float* __restrict__ sTabH,
    int NwLoc, int tid)
{
    const int warp = tid >> 5, lane = tid & 31;
    const float inv_scale = 0.3535533905932738f;
    const int mh = lane / 9, mw = (lane / 3) % 3, md = lane % 3;
    const int tq = mh * 3 + mw;
    const int mbase = mh * 25 + mw * 5 + md + 62;

    for (int wd = warp; wd < NwLoc; wd += 8) {
        if (lane < 27) {
            float* qp = sP + tq * TS + (wd * 3 + md) * 8;
            const float4 q0 = *(const float4*)qp;
            const float4 q1 = *(const float4*)(qp + 4);

            float s[27];
            #pragma unroll
            for (int n = 0; n < 27; n++) {
                const int tn = n / 3, nd = n % 3;
                const float* kp = sP + (9 + tn) * TS + (wd * 3 + nd) * 8;
                const float4 k0 = *(const float4*)kp;
                const float4 k1 = *(const float4*)(kp + 4);
                s[n] = (q0.x * k0.x + q0.y * k0.y + q0.z * k0.z + q0.w * k0.w
                      + q1.x * k1.x + q1.y * k1.y + q1.z * k1.z + q1.w * k1.w)
                       * inv_scale;
            }
            float mxv = s[0];
            #pragma unroll
            for (int n = 1; n < 27; n++) mxv = fmaxf(mxv, s[n]);
            float sum = 0.f;
            #pragma unroll
            for (int n = 0; n < 27; n++) { s[n] = __expf(s[n] - mxv); sum += s[n]; }
            const float inv = 1.0f / sum;
            #pragma unroll
            for (int n = 0; n < 27; n++) {
                const int nh = n / 9, nw = (n / 3) % 3, nd = n % 3;
                s[n] = s[n] * inv + sTabH[mbase - (nh * 25 + nw * 5 + nd)];
            }
            float4 a0 = make_float4(0.f, 0.f, 0.f, 0.f);
            float4 a1 = make_float4(0.f, 0.f, 0.f, 0.f);
            #pragma unroll
            for (int n = 0; n < 27; n++) {
                const int tn = n / 3, nd = n % 3;
                const float* vp = sP + (18 + tn) * TS + (wd * 3 + nd) * 8;
                const float4 v0 = *(const float4*)vp;
                const float4 v1 = *(const float4*)(vp + 4);
                const float sn = s[n];
                a0.x += sn * v0.x; a0.y += sn * v0.y;
                a0.z += sn * v0.z; a0.w += sn * v0.w;
                a1.x += sn * v1.x; a1.y += sn * v1.y;
                a1.z += sn * v1.z; a1.w += sn * v1.w;
            }
            *(float4*)qp       = a0;
            *(float4*)(qp + 4) = a1;
        }
    }
}

// ---------------------------------------------------------------------------
// mainK: br0 attention (cid < 4096) + pooling (rest), co-scheduled.
// ---------------------------------------------------------------------------
__global__ __launch_bounds__(256) void mainK(
    const float* __restrict__ Q, const float* __restrict__ Kt,
    const float* __restrict__ V, const float* __restrict__ tab,
    float* __restrict__ out)
{
    __shared__ float sP[3 * 9 * TS];      // 21600 B
    __shared__ float sTabH[125];

    const int cid = blockIdx.x;
    const int tid = threadIdx.x;

    if (cid >= 4096) {                    // -------- pooling CTA --------
        pool_one((cid - 4096) * 256 + tid, Q, Kt, V);
        return;
    }

    // -------- br0 attention CTA: (bh, line, dhalf) --------
    const int bh    = cid >> 9;
    const int rest  = cid & 511;
    const int line  = rest >> 1;
    const int dhalf = rest & 1;
    const int wh = line >> 4, ww = line & 15;
    const int b = bh >> 1, head = bh & 1;
    const int chbase = b * 64 + head * 8;
    const int h0 = wh * 3, w0 = ww * 3;
    const int dbase = dhalf * 24;

    if (tid < 125) sTabH[tid] = __ldg(tab + tid * 2 + head);

    // gather: 3t * 9tok * 6quads * 8c = 1296 float4 loads
    for (int e = tid; e < 1296; e += 256) {
        const int c    = e & 7;
        const int r    = e >> 3;
        const int pdq  = r % 6;
        const int r2   = r / 6;
        const int token = r2 % 9;
        const int t     = r2 / 9;
        const float* base = (t == 0 ? Q : (t == 1 ? Kt : V))
            + (size_t)(chbase + c) * D3
            + (h0 + token / 3) * D2 + (w0 + token % 3) * D + dbase + 4 * pdq;
        float4 v = __ldg((const float4*)base);
        float* dst = sP + (t * 9 + token) * TS + pdq * 32 + c;
        dst[0] = v.x; dst[8] = v.y; dst[16] = v.z; dst[24] = v.w;
    }
    __syncthreads();

    attn_core(sP, sTabH, 8, tid);
    __syncthreads();

    // scatter: 9tok * 6quads * 8c
    const size_t chD3 = (size_t)chbase * D3;
    for (int e = tid; e < 432; e += 256) {
        const int c    = e & 7;
        const int r    = e >> 3;
        const int pdq  = r % 6;
        const int token = r / 6;
        const float* src = sP + token * TS + pdq * 32 + c;
        float4 v = make_float4(src[0], src[8], src[16], src[24]);
        *(float4*)(out + chD3 + (size_t)c * D3
                   + (h0 + token / 3) * D2 + (w0 + token % 3) * D + dbase + 4 * pdq) = v;
    }
}

// ---------------------------------------------------------------------------
// upsample (br>=1): row-per-thread factored trilinear
// ---------------------------------------------------------------------------
template<int BR, int SPLITS>
__device__ __forceinline__ void upsample(
    const float* __restrict__ sP, const int* __restrict__ sI0,
    const float* __restrict__ sF, float* __restrict__ out,
    int chbase, int h0, int w0, int split, int tid)
{
    constexpr int BW = 3 << BR;
    constexpr int NW = 16 >> BR;
    constexpr int ROWS = 8 * BW * BW;
    constexpr int PER  = ROWS / SPLITS;
    const size_t chD3 = (size_t)chbase * D3;
    const int r0 = split * PER;

    for (int r = r0 + tid; r < r0 + PER; r += 256) {
        const int c   = r / (BW * BW);
        const int rem = r - c * (BW * BW);
        const int lh  = rem / BW;
        const int lw  = rem - lh * BW;

        const int   ih0 = sI0[lh], iw0 = sI0[lw];
        const int   ih1 = (ih0 < 2) ? ih0 + 1 : 2;
        const int   iw1 = (iw0 < 2) ? iw0 + 1 : 2;
        const float fh  = sF[lh],  fw  = sF[lw];

        const int o00 = (ih0 * 3 + iw0) * TS + c;
        const int o01 = (ih0 * 3 + iw1) * TS + c;
        const int o10 = (ih1 * 3 + iw0) * TS + c;
        const int o11 = (ih1 * 3 + iw1) * TS + c;

        float* orow = out + chD3 + (size_t)c * D3 + (h0 + lh) * D2 + (w0 + lw) * D;

        #pragma unroll
        for (int wd = 0; wd < NW; wd++) {
            const int wd3 = wd * 3;
            float T[3];
            #pragma unroll
            for (int id = 0; id < 3; id++) {
                const int po = (wd3 + id) * 8;
                const float t00 = sP[o00 + po], t01 = sP[o01 + po];
                const float t10 = sP[o10 + po], t11 = sP[o11 + po];
                const float a0 = t00 + fw * (t01 - t00);
                const float a1 = t10 + fw * (t11 - t10);
                T[id] = a0 + fh * (a1 - a0);
            }
            float wbuf[BW];
            #pragma unroll
            for (int ld = 0; ld < BW; ld++) {
                const float pos = (float)ld * (2.0f / (float)(BW - 1));
                const int   id0 = (pos >= 2.0f) ? 2 : (int)pos;
                const float fd  = pos - (float)id0;
                const float lo = T[id0];
                const float hi = T[(id0 < 2) ? id0 + 1 : 2];
                wbuf[ld] = lo + fd * (hi - lo);
            }
            float* op = orow + wd * BW;
            if (BW == 6) {
                #pragma unroll
                for (int k = 0; k < 3; k++)
                    *(float2*)(op + k * 2) = make_float2(wbuf[k * 2], wbuf[k * 2 + 1]);
            } else {
                #pragma unroll
                for (int k = 0; k < BW / 4; k++)
                    *(float4*)(op + k * 4) =
                        make_float4(wbuf[k * 4], wbuf[k * 4 + 1],
                                    wbuf[k * 4 + 2], wbuf[k * 4 + 3]);
            }
        }
    }
}

// ---------------------------------------------------------------------------
// restK: br1..3 attention + upsample (consumes g_pool)
// grid 1024: [0,256) br3 split8 | [256,512) br2 split2 | [512,1024) br1
// ---------------------------------------------------------------------------
__global__ __launch_bounds__(256) void restK(
    const float* __restrict__ tab, float* __restrict__ out)
{
    __shared__ float sP[3 * 9 * TS];
    __shared__ float sTabH[125];
    __shared__ int   sI0[24];
    __shared__ float sF[24];

    const int cid = blockIdx.x;
    const int tid = threadIdx.x;
    int br, bh, line, split;
    if (cid < 256) {
        br = 3; bh = cid >> 5;
        const int t5 = cid & 31;
        line = t5 >> 3; split = t5 & 7;
    } else if (cid < 512) {
        br = 2; const int s = cid - 256;
        bh = s >> 5;
        const int t5 = s & 31;
        line = t5 >> 1; split = t5 & 1;
    } else {
        br = 1; const int s = cid - 512;
        bh = s >> 6; line = s & 63; split = 0;
    }

    const int Nw  = 16 >> br;
    const int bw  = 3 << br;
    const int wh = line / Nw, ww = line - wh * Nw;
    const int b = bh >> 1, head = bh & 1;
    const int chbase = b * 64 + br * 16 + head * 8;
    const int h0 = wh * bw, w0 = ww * bw;

    if (tid < 125) sTabH[tid] = __ldg(tab + tid * 2 + head);
    if (tid >= 128 && tid - 128 < bw) {
        const int u = tid - 128;
        const float pos = (float)u * (2.0f / (float)(bw - 1));
        int i0 = (int)pos;
        if (i0 > 2) i0 = 2;
        sI0[u] = i0;
        sF[u]  = pos - (float)i0;
    }

    // gather pooled tokens (c-innermost)
    const int Ppd = 3 * Nw;
    const int per = 72 * Ppd;
    const int Nw2 = Nw * Nw;
    if (br == 3) {                        // Ppd=6 -> float2
        for (int e = tid; e < 648; e += 256) {
            const int c    = e & 7;
            const int r    = e >> 3;
            const int pdp  = r % 3;
            const int r2   = r / 3;
            const int token = r2 % 9;
            const int t     = r2 / 9;
            const float2 v = *(const float2*)(g_pool
                + ((size_t)(t * 8 + bh) * 4 + line) * 432
                + (c * 9 + token) * 6 + 2 * pdp);
            float* dst = sP + (t * 9 + token) * TS + pdp * 16 + c;
            dst[0] = v.x; dst[8] = v.y;
        }
    } else {                              // Ppd=12/24 -> float4
        const int pk = Ppd >> 2;
        const int base_br = (br == 2) ? S3 : S3 + S2;
        const int tot = 216 * pk;         // 3*9*8*pk
        for (int e = tid; e < tot; e += 256) {
            const int c    = e & 7;
            const int r    = e >> 3;
            const int pdq  = r % pk;
            const int r2   = r / pk;
            const int token = r2 % 9;
            const int t     = r2 / 9;
            const float4 v = *(const float4*)(g_pool + base_br
                + ((size_t)(t * 8 + bh) * Nw2 + line) * per
                + (c * 9 + token) * Ppd + 4 * pdq);
            float* dst = sP + (t * 9 + token) * TS + pdq * 32 + c;
            dst[0] = v.x; dst[8] = v.y; dst[16] = v.z; dst[24] = v.w;
        }
    }
    __syncthreads();

    attn_core(sP, sTabH, Nw, tid);
    __syncthreads();

    if (br == 1)      upsample<1, 1>(sP, sI0, sF, out, chbase, h0, w0, split, tid);
    else if (br == 2) upsample<2, 2>(sP, sI0, sF, out, chbase, h0, w0, split, tid);
    else              upsample<3, 8>(sP, sI0, sF, out, chbase, h0, w0, split, tid);
}

extern "C" void kernel_launch(void* const* d_in, const int* in_sizes, int n_in,
                              void* d_out, int out_size)
{
    const float* Q   = (const float*)d_in[0];
    const float* K   = (const float*)d_in[1];
    const float* V   = (const float*)d_in[2];
    const float* tab = (const float*)d_in[3];
    float* out = (float*)d_out;

    mainK<<<4096 + POOL_CTAS, 256>>>(Q, K, V, tab, out);
    restK<<<1024, 256>>>(tab, out);
}

// round 8
// speedup vs baseline: 2.9101x; 1.0383x over previous
#include <cuda_runtime.h>
#include <math.h>

#define D  48
#define D2 (48*48)
#define D3 (48*48*48)
#define TS 200     // smem token-row stride (floats): up to 24pd*8c=192, +8 pad

// ---------------------------------------------------------------------------
// attention core: warp-per-window, c-innermost smem, windows [0, NwLoc)
// ---------------------------------------------------------------------------
__device__ __forceinline__ void attn_core(
    float* __restrict__ sP, const float* __restrict__ sTabH,
    int NwLoc, int tid)
{
    const int warp = tid >> 5, lane = tid & 31;
    const float inv_scale = 0.3535533905932738f;
    const int mh = lane / 9, mw = (lane / 3) % 3, md = lane % 3;
    const int tq = mh * 3 + mw;
    const int mbase = mh * 25 + mw * 5 + md + 62;

    for (int wd = warp; wd < NwLoc; wd += 8) {
        if (lane < 27) {
            float* qp = sP + tq * TS + (wd * 3 + md) * 8;
            const float4 q0 = *(const float4*)qp;
            const float4 q1 = *(const float4*)(qp + 4);

            float s[27];
            #pragma unroll
            for (int n = 0; n < 27; n++) {
                const int tn = n / 3, nd = n % 3;
                const float* kp = sP + (9 + tn) * TS + (wd * 3 + nd) * 8;
                const float4 k0 = *(const float4*)kp;
                const float4 k1 = *(const float4*)(kp + 4);
                s[n] = (q0.x * k0.x + q0.y * k0.y + q0.z * k0.z + q0.w * k0.w
                      + q1.x * k1.x + q1.y * k1.y + q1.z * k1.z + q1.w * k1.w)
                       * inv_scale;
            }
            float mxv = s[0];
            #pragma unroll
            for (int n = 1; n < 27; n++) mxv = fmaxf(mxv, s[n]);
            float sum = 0.f;
            #pragma unroll
            for (int n = 0; n < 27; n++) { s[n] = __expf(s[n] - mxv); sum += s[n]; }
            const float inv = 1.0f / sum;
            #pragma unroll
            for (int n = 0; n < 27; n++) {
                const int nh = n / 9, nw = (n / 3) % 3, nd = n % 3;
                s[n] = s[n] * inv + sTabH[mbase - (nh * 25 + nw * 5 + nd)];
            }
            float4 a0 = make_float4(0.f, 0.f, 0.f, 0.f);
            float4 a1 = make_float4(0.f, 0.f, 0.f, 0.f);
            #pragma unroll
            for (int n = 0; n < 27; n++) {
                const int tn = n / 3, nd = n % 3;
                const float* vp = sP + (18 + tn) * TS + (wd * 3 + nd) * 8;
                const float4 v0 = *(const float4*)vp;
                const float4 v1 = *(const float4*)(vp + 4);
                const float sn = s[n];
                a0.x += sn * v0.x; a0.y += sn * v0.y;
                a0.z += sn * v0.z; a0.w += sn * v0.w;
                a1.x += sn * v1.x; a1.y += sn * v1.y;
                a1.z += sn * v1.z; a1.w += sn * v1.w;
            }
            *(float4*)qp       = a0;
            *(float4*)(qp + 4) = a1;
        }
    }
}

// ---------------------------------------------------------------------------
// upsample (br>=1): row-per-thread factored trilinear; local windows [0,NWLOC)
// ---------------------------------------------------------------------------
template<int BR, int NWLOC>
__device__ __forceinline__ void upsample(
    const float* __restrict__ sP, const int* __restrict__ sI0,
    const float* __restrict__ sF, float* __restrict__ out,
    int chbase, int h0, int w0, int dhalf, int tid)
{
    constexpr int BW = 3 << BR;
    constexpr int ROWS = 8 * BW * BW;
    const size_t chD3 = (size_t)chbase * D3;
    const int dbase = dhalf * NWLOC * BW;

    for (int r = tid; r < ROWS; r += 256) {
        const int c   = r / (BW * BW);
        const int rem = r - c * (BW * BW);
        const int lh  = rem / BW;
        const int lw  = rem - lh * BW;

        const int   ih0 = sI0[lh], iw0 = sI0[lw];
        const int   ih1 = (ih0 < 2) ? ih0 + 1 : 2;
        const int   iw1 = (iw0 < 2) ? iw0 + 1 : 2;
        const float fh  = sF[lh],  fw  = sF[lw];

        const int o00 = (ih0 * 3 + iw0) * TS + c;
        const int o01 = (ih0 * 3 + iw1) * TS + c;
        const int o10 = (ih1 * 3 + iw0) * TS + c;
        const int o11 = (ih1 * 3 + iw1) * TS + c;

        float* orow = out + chD3 + (size_t)c * D3
                      + (h0 + lh) * D2 + (w0 + lw) * D + dbase;

        #pragma unroll
        for (int wd = 0; wd < NWLOC; wd++) {
            const int wd3 = wd * 3;
            float T[3];
            #pragma unroll
            for (int id = 0; id < 3; id++) {
                const int po = (wd3 + id) * 8;
                const float t00 = sP[o00 + po], t01 = sP[o01 + po];
                const float t10 = sP[o10 + po], t11 = sP[o11 + po];
                const float a0 = t00 + fw * (t01 - t00);
                const float a1 = t10 + fw * (t11 - t10);
                T[id] = a0 + fh * (a1 - a0);
            }
            float wbuf[BW];
            #pragma unroll
            for (int ld = 0; ld < BW; ld++) {
                const float pos = (float)ld * (2.0f / (float)(BW - 1));
                const int   id0 = (pos >= 2.0f) ? 2 : (int)pos;
                const float fd  = pos - (float)id0;
                const float lo = T[id0];
                const float hi = T[(id0 < 2) ? id0 + 1 : 2];
                wbuf[ld] = lo + fd * (hi - lo);
            }
            float* op = orow + wd * BW;
            if (BW == 6) {
                #pragma unroll
                for (int k = 0; k < 3; k++)
                    *(float2*)(op + k * 2) = make_float2(wbuf[k * 2], wbuf[k * 2 + 1]);
            } else {
                #pragma unroll
                for (int k = 0; k < BW / 4; k++)
                    *(float4*)(op + k * 4) =
                        make_float4(wbuf[k * 4], wbuf[k * 4 + 1],
                                    wbuf[k * 4 + 2], wbuf[k * 4 + 3]);
            }
        }
    }
}

// ---------------------------------------------------------------------------
// fusedK: pool-in-CTA + attention + upsample, all branches, one launch.
// grid 4800: [0,64) br3 (d-split x2) | [64,192) br2 | [192,704) br1 |
//            [704,4800) br0 (d-split x2)
// ---------------------------------------------------------------------------
__global__ __launch_bounds__(256) void fusedK(
    const float* __restrict__ Q, const float* __restrict__ Kt,
    const float* __restrict__ V, const float* __restrict__ tab,
    float* __restrict__ out)
{
    __shared__ float sP[27 * TS];         // 21600 B
    __shared__ float sTabH[125];
    __shared__ int   sI0[24];
    __shared__ float sF[24];

    const int cid = blockIdx.x;
    const int tid = threadIdx.x;

    int br, bh, line, dhalf;
    if (cid < 64) {
        br = 3; bh = cid >> 3;
        const int s = cid & 7;
        line = s >> 1; dhalf = s & 1;
    } else if (cid < 192) {
        br = 2; const int s = cid - 64;
        bh = s >> 4; line = s & 15; dhalf = 0;
    } else if (cid < 704) {
        br = 1; const int s = cid - 192;
        bh = s >> 6; line = s & 63; dhalf = 0;
    } else {
        br = 0; const int s = cid - 704;
        bh = s >> 9;
        const int rest = s & 511;
        line = rest >> 1; dhalf = rest & 1;
    }

    const int Nw = 16 >> br;
    const int bw = 3 << br;
    const int wh = line / Nw, ww = line - wh * Nw;
    const int b = bh >> 1, head = bh & 1;
    const int chbase = b * 64 + br * 16 + head * 8;
    const int h0 = wh * bw, w0 = ww * bw;

    if (tid < 125) sTabH[tid] = __ldg(tab + tid * 2 + head);
    if (tid >= 128 && tid - 128 < bw) {
        const int u = tid - 128;
        const float pos = (float)u * (2.0f / (float)(bw - 1));
        int i0 = (int)pos;
        if (i0 > 2) i0 = 2;
        sI0[u] = i0;
        sF[u]  = pos - (float)i0;
    }

    // ---- pool raw input directly into c-innermost smem ----
    if (br == 0) {
        const int dbase = dhalf * 24;
        for (int e = tid; e < 1296; e += 256) {           // 3t*9tok*6q*8c
            const int c    = e & 7;
            const int r    = e >> 3;
            const int pdq  = r % 6;
            const int r2   = r / 6;
            const int token = r2 % 9;
            const int t     = r2 / 9;
            const float* base = (t == 0 ? Q : (t == 1 ? Kt : V))
                + (size_t)(chbase + c) * D3
                + (h0 + token / 3) * D2 + (w0 + token % 3) * D + dbase + 4 * pdq;
            float4 v = __ldg((const float4*)base);
            float* dst = sP + (t * 9 + token) * TS + pdq * 32 + c;
            dst[0] = v.x; dst[8] = v.y; dst[16] = v.z; dst[24] = v.w;
        }
    } else if (br == 1) {                 // sw=2, PDL=24
        for (int e = tid; e < 5184; e += 256) {
            const int c    = e & 7;
            const int r    = e >> 3;
            const int pdl  = r % 24;
            const int r2   = r / 24;
            const int token = r2 % 9;
            const int t     = r2 / 9;
            const float* base = (t == 0 ? Q : (t == 1 ? Kt : V))
                + (size_t)(chbase + c) * D3;
            const int hh  = h0 + (token / 3) * 2;
            const int wwp = w0 + (token % 3) * 2;
            const float* p = base + hh * D2 + wwp * D + pdl * 2;
            float mx = -1e30f;
            #pragma unroll
            for (int dh = 0; dh < 2; dh++)
                #pragma unroll
                for (int dw = 0; dw < 2; dw++) {
                    float2 a = __ldg((const float2*)(p + dh * D2 + dw * D));
                    mx = fmaxf(mx, fmaxf(a.x, a.y));
                }
            sP[(t * 9 + token) * TS + pdl * 8 + c] = mx;
        }
    } else if (br == 2) {                 // sw=4, PDL=12
        for (int e = tid; e < 2592; e += 256) {
            const int c    = e & 7;
            const int r    = e >> 3;
            const int pdl  = r % 12;
            const int r2   = r / 12;
            const int token = r2 % 9;
            const int t     = r2 / 9;
            const float* base = (t == 0 ? Q : (t == 1 ? Kt : V))
                + (size_t)(chbase + c) * D3;
            const int hh  = h0 + (token / 3) * 4;
            const int wwp = w0 + (token % 3) * 4;
            const float* p = base + hh * D2 + wwp * D + pdl * 4;
            float mx = -1e30f;
            #pragma unroll
            for (int dh = 0; dh < 4; dh++)
                #pragma unroll
                for (int dw = 0; dw < 4; dw++) {
                    float4 a = __ldg((const float4*)(p + dh * D2 + dw * D));
                    mx = fmaxf(mx, fmaxf(fmaxf(a.x, a.y), fmaxf(a.z, a.w)));
                }
            sP[(t * 9 + token) * TS + pdl * 8 + c] = mx;
        }
    } else {                              // br3: sw=8, PDL=3 (d-half)
        for (int e = tid; e < 648; e += 256) {
            const int c    = e & 7;
            const int r    = e >> 3;
            const int pdl  = r % 3;
            const int r2   = r / 3;
            const int token = r2 % 9;
            const int t     = r2 / 9;
            const float* base = (t == 0 ? Q : (t == 1 ? Kt : V))
                + (size_t)(chbase + c) * D3;
            const int hh  = h0 + (token / 3) * 8;
            const int wwp = w0 + (token % 3) * 8;
            const float* p = base + hh * D2 + wwp * D + dhalf * 24 + pdl * 8;
            float mx = -1e30f;
            for (int dh = 0; dh < 8; dh++) {
                const float* rowb = p + dh * D2;
                #pragma unroll
                for (int dw = 0; dw < 8; dw++) {
                    float4 a = __ldg((const float4*)(rowb + dw * D));
                    float4 bq = __ldg((const float4*)(rowb + dw * D + 4));
                    mx = fmaxf(mx, fmaxf(fmaxf(a.x, a.y), fmaxf(a.z, a.w)));
                    mx = fmaxf(mx, fmaxf(fmaxf(bq.x, bq.y), fmaxf(bq.z, bq.w)));
                }
            }
            sP[(t * 9 + token) * TS + pdl * 8 + c] = mx;
        }
    }
    __syncthreads();

    // ---- attention ----
    const int NwLoc = (br == 0) ? 8 : ((br == 3) ? 1 : Nw);
    attn_core(sP, sTabH, NwLoc, tid);
    __syncthreads();

    // ---- scatter / upsample ----
    if (br == 0) {
        const int dbase = dhalf * 24;
        const size_t chD3 = (size_t)chbase * D3;
        for (int e = tid; e < 432; e += 256) {
            const int c    = e & 7;
            const int r    = e >> 3;
            const int pdq  = r % 6;
            const int token = r / 6;
            const float* src = sP + token * TS + pdq * 32 + c;
            float4 v = make_float4(src[0], src[8], src[16], src[24]);
            *(float4*)(out + chD3 + (size_t)c * D3
                       + (h0 + token / 3) * D2 + (w0 + token % 3) * D
                       + dbase + 4 * pdq) = v;
        }
    } else if (br == 1) {
        upsample<1, 8>(sP, sI0, sF, out, chbase, h0, w0, 0, tid);
    } else if (br == 2) {
        upsample<2, 4>(sP, sI0, sF, out, chbase, h0, w0, 0, tid);
    } else {
        upsample<3, 1>(sP, sI0, sF, out, chbase, h0, w0, dhalf, tid);
    }
}

extern "C" void kernel_launch(void* const* d_in, const int* in_sizes, int n_in,
                              void* d_out, int out_size)
{
    const float* Q   = (const float*)d_in[0];
    const float* K   = (const float*)d_in[1];
    const float* V   = (const float*)d_in[2];
    const float* tab = (const float*)d_in[3];
    float* out = (float*)d_out;

    fusedK<<<4800, 256>>>(Q, K, V, tab, out);
}